// round 1
// baseline (speedup 1.0000x reference)
#include <cuda_runtime.h>
#include <cuda_bf16.h>

#define B_    16
#define D_    512
#define HW_   1024
#define CD_   256
#define K_    8192
#define NTOK  (B_ * HW_)        /* 16384 */
#define OUT_N (B_ * D_ * HW_)   /* 8388608 */

// ---------------- scratch (no allocations allowed) ----------------
__device__ float  g_z[NTOK * CD_];     // 16 MB projected z
__device__ float  g_cnorm[K_];         // ||e_k||^2
__device__ int    g_idx[NTOK];         // argmin indices
__device__ double g_loss;              // commitment-loss accumulator

// ---------------- ||e_k||^2 : one warp per code ----------------
__global__ void cnorm_kernel(const float* __restrict__ E) {
    int warp = (blockIdx.x * blockDim.x + threadIdx.x) >> 5;
    int lane = threadIdx.x & 31;
    if (warp >= K_) return;
    const float4* row = (const float4*)(E + (size_t)warp * CD_);
    float4 a = row[lane * 2];
    float4 b = row[lane * 2 + 1];
    float s = a.x*a.x + a.y*a.y + a.z*a.z + a.w*a.w
            + b.x*b.x + b.y*b.y + b.z*b.z + b.w*b.w;
    #pragma unroll
    for (int o = 16; o; o >>= 1) s += __shfl_down_sync(0xffffffffu, s, o);
    if (lane == 0) g_cnorm[warp] = s;
}

__global__ void zero_loss_kernel() { g_loss = 0.0; }

// ---------------- GEMM1: z = x^T @ W_in^T + b_in ----------------
// x is [B][D][HW]; token t = b*1024 + n reads x[b][d][n] (t-contiguous -> coalesced)
// tile 64x64, BK=16, 256 threads, 4x4 register tile, double-buffered
__global__ __launch_bounds__(256, 2)
void proj_in_kernel(const float* __restrict__ x,
                    const float* __restrict__ Win,
                    const float* __restrict__ bin) {
    __shared__ float As[2][16][64];
    __shared__ float Bs[2][16][64];
    int tid = threadIdx.x;
    int tx = tid & 15, ty = tid >> 4;
    int t0 = blockIdx.x * 64, c0 = blockIdx.y * 64;
    int batch = t0 >> 10;
    int n0 = t0 & 1023;
    const float* xb = x + (size_t)batch * (D_ * HW_);

    float acc[4][4];
    #pragma unroll
    for (int i = 0; i < 4; i++)
        #pragma unroll
        for (int j = 0; j < 4; j++) acc[i][j] = 0.f;

    int a_t  = tid & 63;      // token in tile
    int a_k  = tid >> 6;      // 0..3, k = a_k + 4*i
    int b_c  = tid >> 2;      // 0..63
    int b_k4 = tid & 3;

    float pa[4]; float4 pb;
    #pragma unroll
    for (int i = 0; i < 4; i++)
        pa[i] = xb[(a_k + 4 * i) * HW_ + n0 + a_t];
    pb = *(const float4*)(Win + (size_t)(c0 + b_c) * D_ + b_k4 * 4);

    #pragma unroll
    for (int i = 0; i < 4; i++) As[0][a_k + 4 * i][a_t] = pa[i];
    Bs[0][b_k4 * 4 + 0][b_c] = pb.x; Bs[0][b_k4 * 4 + 1][b_c] = pb.y;
    Bs[0][b_k4 * 4 + 2][b_c] = pb.z; Bs[0][b_k4 * 4 + 3][b_c] = pb.w;
    __syncthreads();

    const int NCH = D_ / 16;  // 32
    #pragma unroll 1
    for (int ch = 0; ch < NCH; ch++) {
        int buf = ch & 1;
        if (ch + 1 < NCH) {
            int d0 = (ch + 1) * 16;
            #pragma unroll
            for (int i = 0; i < 4; i++)
                pa[i] = xb[(d0 + a_k + 4 * i) * HW_ + n0 + a_t];
            pb = *(const float4*)(Win + (size_t)(c0 + b_c) * D_ + d0 + b_k4 * 4);
        }
        #pragma unroll
        for (int kk = 0; kk < 16; kk++) {
            float4 av = *(const float4*)(&As[buf][kk][ty * 4]);
            float4 bv = *(const float4*)(&Bs[buf][kk][tx * 4]);
            float a[4] = {av.x, av.y, av.z, av.w};
            float b[4] = {bv.x, bv.y, bv.z, bv.w};
            #pragma unroll
            for (int i = 0; i < 4; i++)
                #pragma unroll
                for (int j = 0; j < 4; j++) acc[i][j] += a[i] * b[j];
        }
        if (ch + 1 < NCH) {
            int ob = buf ^ 1;
            #pragma unroll
            for (int i = 0; i < 4; i++) As[ob][a_k + 4 * i][a_t] = pa[i];
            Bs[ob][b_k4 * 4 + 0][b_c] = pb.x; Bs[ob][b_k4 * 4 + 1][b_c] = pb.y;
            Bs[ob][b_k4 * 4 + 2][b_c] = pb.z; Bs[ob][b_k4 * 4 + 3][b_c] = pb.w;
            __syncthreads();
        }
    }

    float4 bb = *(const float4*)(bin + c0 + tx * 4);
    float bv[4] = {bb.x, bb.y, bb.z, bb.w};
    #pragma unroll
    for (int i = 0; i < 4; i++) {
        float4 v;
        v.x = acc[i][0] + bv[0]; v.y = acc[i][1] + bv[1];
        v.z = acc[i][2] + bv[2]; v.w = acc[i][3] + bv[3];
        *(float4*)(g_z + (size_t)(t0 + ty * 4 + i) * CD_ + c0 + tx * 4) = v;
    }
}

// ---------------- fused distance GEMM + argmin ----------------
// Block: 128 tokens (Z tile persistent in smem, 128KB) x all 8192 codes,
// 64-code tiles, BK=16 double-buffered. Thread tile 8 tokens x 4 codes.
// score = cnorm[k] - 2 * (z . e_k); running per-thread (min,idx).
__global__ __launch_bounds__(256, 1)
void argmin_kernel(const float* __restrict__ E) {
    extern __shared__ float sm[];
    float* Zs = sm;                      // [256][128]
    float* Es = sm + 256 * 128;          // 2 x [16][64]

    int tid = threadIdx.x;
    int tx = tid & 15, ty = tid >> 4;
    int t0 = blockIdx.x * 128;

    // load Z tile transposed: Zs[c][t]
    for (int i = tid; i < 128 * CD_ / 4; i += 256) {   // 8192 float4
        int t  = i >> 6;
        int c4 = i & 63;
        float4 v = *(const float4*)(g_z + (size_t)(t0 + t) * CD_ + c4 * 4);
        Zs[(c4 * 4 + 0) * 128 + t] = v.x;
        Zs[(c4 * 4 + 1) * 128 + t] = v.y;
        Zs[(c4 * 4 + 2) * 128 + t] = v.z;
        Zs[(c4 * 4 + 3) * 128 + t] = v.w;
    }

    float bestV[8]; int bestI[8];
    #pragma unroll
    for (int i = 0; i < 8; i++) { bestV[i] = 3.402823466e38f; bestI[i] = 0; }
    float acc[8][4];
    #pragma unroll
    for (int i = 0; i < 8; i++)
        #pragma unroll
        for (int j = 0; j < 4; j++) acc[i][j] = 0.f;

    int code_l = tid >> 2;   // 0..63
    int c4     = tid & 3;

    // prefetch chunk 0 (code tile 0, c-dims 0..15)
    float4 pf = *(const float4*)(E + (size_t)code_l * CD_ + c4 * 4);
    __syncthreads();                       // Zs visible
    {
        float* Eb = Es;
        Eb[(c4 * 4 + 0) * 64 + code_l] = pf.x;
        Eb[(c4 * 4 + 1) * 64 + code_l] = pf.y;
        Eb[(c4 * 4 + 2) * 64 + code_l] = pf.z;
        Eb[(c4 * 4 + 3) * 64 + code_l] = pf.w;
    }
    __syncthreads();

    const int NCH = (K_ / 64) * (CD_ / 16);   // 2048 chunks
    #pragma unroll 1
    for (int ch = 0; ch < NCH; ch++) {
        int buf = ch & 1;
        float4 nxt;
        if (ch + 1 < NCH) {
            int nk = (ch + 1) >> 4;
            int nc = (ch + 1) & 15;
            nxt = *(const float4*)(E + (size_t)(nk * 64 + code_l) * CD_ + nc * 16 + c4 * 4);
        }
        const float* Eb = Es + buf * 16 * 64;
        int crow = (ch & 15) * 16;
        #pragma unroll
        for (int kk = 0; kk < 16; kk++) {
            float4 a0 = *(const float4*)(Zs + (crow + kk) * 128 + ty * 8);
            float4 a1 = *(const float4*)(Zs + (crow + kk) * 128 + ty * 8 + 4);
            float4 bvv = *(const float4*)(Eb + kk * 64 + tx * 4);
            float a[8] = {a0.x, a0.y, a0.z, a0.w, a1.x, a1.y, a1.z, a1.w};
            float b[4] = {bvv.x, bvv.y, bvv.z, bvv.w};
            #pragma unroll
            for (int i = 0; i < 8; i++)
                #pragma unroll
                for (int j = 0; j < 4; j++) acc[i][j] += a[i] * b[j];
        }
        if ((ch & 15) == 15) {
            int kt = ch >> 4;
            float4 cn = *(const float4*)(g_cnorm + kt * 64 + tx * 4);
            float cnv[4] = {cn.x, cn.y, cn.z, cn.w};
            #pragma unroll
            for (int i = 0; i < 8; i++) {
                #pragma unroll
                for (int j = 0; j < 4; j++) {
                    float s = cnv[j] - 2.0f * acc[i][j];
                    int k = kt * 64 + tx * 4 + j;
                    if (s < bestV[i]) { bestV[i] = s; bestI[i] = k; }
                    acc[i][j] = 0.f;
                }
            }
        }
        if (ch + 1 < NCH) {
            float* Eo = Es + (buf ^ 1) * 16 * 64;
            Eo[(c4 * 4 + 0) * 64 + code_l] = nxt.x;
            Eo[(c4 * 4 + 1) * 64 + code_l] = nxt.y;
            Eo[(c4 * 4 + 2) * 64 + code_l] = nxt.z;
            Eo[(c4 * 4 + 3) * 64 + code_l] = nxt.w;
            __syncthreads();
        }
    }

    // reduce across tx (same-ty = half-warp, width 16); ties -> lower index
    #pragma unroll
    for (int i = 0; i < 8; i++) {
        float v = bestV[i]; int bi = bestI[i];
        #pragma unroll
        for (int off = 8; off; off >>= 1) {
            float ov = __shfl_down_sync(0xffffffffu, v, off, 16);
            int   oi = __shfl_down_sync(0xffffffffu, bi, off, 16);
            if (ov < v || (ov == v && oi < bi)) { v = ov; bi = oi; }
        }
        if (tx == 0) g_idx[t0 + ty * 8 + i] = bi;
    }
}

// ---------------- GEMM2: out = q @ W_out^T + b_out, transposed store ----------------
__global__ __launch_bounds__(256, 2)
void proj_out_kernel(const float* __restrict__ E,
                     const float* __restrict__ Wout,
                     const float* __restrict__ bout,
                     float* __restrict__ out) {
    __shared__ float As[2][16][64];
    __shared__ float Bs[2][16][64];
    __shared__ int sIdx[64];
    int tid = threadIdx.x;
    int tx = tid & 15, ty = tid >> 4;
    int t0 = blockIdx.x * 64, c0 = blockIdx.y * 64;   // c0 = output-dim tile
    if (tid < 64) sIdx[tid] = g_idx[t0 + tid];
    __syncthreads();

    int a_t = tid >> 2, a_k4 = tid & 3;
    int b_c = tid >> 2, b_k4 = tid & 3;
    size_t rowA = (size_t)sIdx[a_t] * CD_;

    float acc[4][4];
    #pragma unroll
    for (int i = 0; i < 4; i++)
        #pragma unroll
        for (int j = 0; j < 4; j++) acc[i][j] = 0.f;

    float4 pa = *(const float4*)(E + rowA + a_k4 * 4);
    float4 pb = *(const float4*)(Wout + (size_t)(c0 + b_c) * CD_ + b_k4 * 4);
    As[0][a_k4 * 4 + 0][a_t] = pa.x; As[0][a_k4 * 4 + 1][a_t] = pa.y;
    As[0][a_k4 * 4 + 2][a_t] = pa.z; As[0][a_k4 * 4 + 3][a_t] = pa.w;
    Bs[0][b_k4 * 4 + 0][b_c] = pb.x; Bs[0][b_k4 * 4 + 1][b_c] = pb.y;
    Bs[0][b_k4 * 4 + 2][b_c] = pb.z; Bs[0][b_k4 * 4 + 3][b_c] = pb.w;
    __syncthreads();

    const int NCH = CD_ / 16;  // 16
    #pragma unroll 1
    for (int ch = 0; ch < NCH; ch++) {
        int buf = ch & 1;
        if (ch + 1 < NCH) {
            int k0 = (ch + 1) * 16;
            pa = *(const float4*)(E + rowA + k0 + a_k4 * 4);
            pb = *(const float4*)(Wout + (size_t)(c0 + b_c) * CD_ + k0 + b_k4 * 4);
        }
        #pragma unroll
        for (int kk = 0; kk < 16; kk++) {
            float4 av = *(const float4*)(&As[buf][kk][ty * 4]);
            float4 bv = *(const float4*)(&Bs[buf][kk][tx * 4]);
            float a[4] = {av.x, av.y, av.z, av.w};
            float b[4] = {bv.x, bv.y, bv.z, bv.w};
            #pragma unroll
            for (int i = 0; i < 4; i++)
                #pragma unroll
                for (int j = 0; j < 4; j++) acc[i][j] += a[i] * b[j];
        }
        if (ch + 1 < NCH) {
            int ob = buf ^ 1;
            As[ob][a_k4 * 4 + 0][a_t] = pa.x; As[ob][a_k4 * 4 + 1][a_t] = pa.y;
            As[ob][a_k4 * 4 + 2][a_t] = pa.z; As[ob][a_k4 * 4 + 3][a_t] = pa.w;
            Bs[ob][b_k4 * 4 + 0][b_c] = pb.x; Bs[ob][b_k4 * 4 + 1][b_c] = pb.y;
            Bs[ob][b_k4 * 4 + 2][b_c] = pb.z; Bs[ob][b_k4 * 4 + 3][b_c] = pb.w;
            __syncthreads();
        }
    }

    int batch = t0 >> 10;
    int n0 = t0 & 1023;
    float* ob = out + (size_t)batch * (D_ * HW_);
    #pragma unroll
    for (int j = 0; j < 4; j++) {
        int dcol = c0 + tx * 4 + j;
        float bo = bout[dcol];
        float4 v;
        v.x = acc[0][j] + bo; v.y = acc[1][j] + bo;
        v.z = acc[2][j] + bo; v.w = acc[3][j] + bo;
        *(float4*)(ob + (size_t)dcol * HW_ + n0 + ty * 4) = v;
    }
}

// ---------------- commitment loss ----------------
__global__ void loss_kernel(const float* __restrict__ E) {
    __shared__ float red[256];
    int tid = threadIdx.x;
    float s = 0.f;
    int stride = gridDim.x * blockDim.x;
    for (int e = blockIdx.x * blockDim.x + tid; e < NTOK * CD_; e += stride) {
        int t = e >> 8;
        float d = E[(size_t)g_idx[t] * CD_ + (e & 255)] - g_z[e];
        s += d * d;
    }
    red[tid] = s; __syncthreads();
    for (int o = 128; o; o >>= 1) {
        if (tid < o) red[tid] += red[tid + o];
        __syncthreads();
    }
    if (tid == 0) atomicAdd(&g_loss, (double)red[0]);
}

__global__ void finalize_kernel(float* __restrict__ out, int writeIdx, int writeLoss) {
    int i = blockIdx.x * blockDim.x + threadIdx.x;
    if (writeIdx && i < NTOK) out[OUT_N + i] = (float)g_idx[i];
    if (writeLoss && i == 0)
        out[OUT_N + NTOK] = (float)(g_loss * (1.0 / (double)(NTOK * CD_)));
}

// ---------------- launch ----------------
extern "C" void kernel_launch(void* const* d_in, const int* in_sizes, int n_in,
                              void* d_out, int out_size) {
    const float* x    = (const float*)d_in[0];
    const float* Win  = (const float*)d_in[1];
    const float* bin  = (const float*)d_in[2];
    const float* Wout = (const float*)d_in[3];
    const float* bout = (const float*)d_in[4];
    const float* cb   = (const float*)d_in[5];
    float* out = (float*)d_out;

    const int ARGMIN_SMEM = (256 * 128 + 2 * 16 * 64) * 4;  // 139264 B
    cudaFuncSetAttribute(argmin_kernel,
                         cudaFuncAttributeMaxDynamicSharedMemorySize, ARGMIN_SMEM);

    zero_loss_kernel<<<1, 1>>>();
    cnorm_kernel<<<K_ / 8, 256>>>(cb);

    dim3 g1(NTOK / 64, CD_ / 64);
    proj_in_kernel<<<g1, 256>>>(x, Win, bin);

    argmin_kernel<<<NTOK / 128, 256, ARGMIN_SMEM>>>(cb);

    dim3 g2(NTOK / 64, D_ / 64);
    proj_out_kernel<<<g2, 256>>>(cb, Wout, bout, out);

    loss_kernel<<<256, 256>>>(cb);

    int writeIdx  = (out_size >= OUT_N + NTOK) ? 1 : 0;
    int writeLoss = (out_size >= OUT_N + NTOK + 1) ? 1 : 0;
    finalize_kernel<<<(NTOK + 255) / 256, 256>>>(out, writeIdx, writeLoss);
}

// round 2
// speedup vs baseline: 1.0002x; 1.0002x over previous
#include <cuda_runtime.h>
#include <cuda_bf16.h>

#define B_    16
#define D_    512
#define HW_   1024
#define CD_   256
#define K_    8192
#define NTOK  (B_ * HW_)        /* 16384 */
#define OUT_N (B_ * D_ * HW_)   /* 8388608 */

// ---------------- scratch (no allocations allowed) ----------------
__device__ float  g_z[NTOK * CD_];     // 16 MB projected z
__device__ float  g_cnorm[K_];         // ||e_k||^2
__device__ int    g_idx[NTOK];         // argmin indices
__device__ double g_loss;              // commitment-loss accumulator

// ---------------- ||e_k||^2 : one warp per code ----------------
__global__ void cnorm_kernel(const float* __restrict__ E) {
    int warp = (blockIdx.x * blockDim.x + threadIdx.x) >> 5;
    int lane = threadIdx.x & 31;
    if (warp >= K_) return;
    const float4* row = (const float4*)(E + (size_t)warp * CD_);
    float4 a = row[lane * 2];
    float4 b = row[lane * 2 + 1];
    float s = a.x*a.x + a.y*a.y + a.z*a.z + a.w*a.w
            + b.x*b.x + b.y*b.y + b.z*b.z + b.w*b.w;
    #pragma unroll
    for (int o = 16; o; o >>= 1) s += __shfl_down_sync(0xffffffffu, s, o);
    if (lane == 0) g_cnorm[warp] = s;
}

__global__ void zero_loss_kernel() { g_loss = 0.0; }

// ---------------- GEMM1: z = x^T @ W_in^T + b_in ----------------
// x is [B][D][HW]; token t = b*1024 + n reads x[b][d][n] (t-contiguous -> coalesced)
// tile 64x64, BK=16, 256 threads, 4x4 register tile, double-buffered
__global__ __launch_bounds__(256, 2)
void proj_in_kernel(const float* __restrict__ x,
                    const float* __restrict__ Win,
                    const float* __restrict__ bin) {
    __shared__ float As[2][16][64];
    __shared__ float Bs[2][16][64];
    int tid = threadIdx.x;
    int tx = tid & 15, ty = tid >> 4;
    int t0 = blockIdx.x * 64, c0 = blockIdx.y * 64;
    int batch = t0 >> 10;
    int n0 = t0 & 1023;
    const float* xb = x + (size_t)batch * (D_ * HW_);

    float acc[4][4];
    #pragma unroll
    for (int i = 0; i < 4; i++)
        #pragma unroll
        for (int j = 0; j < 4; j++) acc[i][j] = 0.f;

    int a_t  = tid & 63;      // token in tile
    int a_k  = tid >> 6;      // 0..3, k = a_k + 4*i
    int b_c  = tid >> 2;      // 0..63
    int b_k4 = tid & 3;

    float pa[4]; float4 pb;
    #pragma unroll
    for (int i = 0; i < 4; i++)
        pa[i] = xb[(a_k + 4 * i) * HW_ + n0 + a_t];
    pb = *(const float4*)(Win + (size_t)(c0 + b_c) * D_ + b_k4 * 4);

    #pragma unroll
    for (int i = 0; i < 4; i++) As[0][a_k + 4 * i][a_t] = pa[i];
    Bs[0][b_k4 * 4 + 0][b_c] = pb.x; Bs[0][b_k4 * 4 + 1][b_c] = pb.y;
    Bs[0][b_k4 * 4 + 2][b_c] = pb.z; Bs[0][b_k4 * 4 + 3][b_c] = pb.w;
    __syncthreads();

    const int NCH = D_ / 16;  // 32
    #pragma unroll 1
    for (int ch = 0; ch < NCH; ch++) {
        int buf = ch & 1;
        if (ch + 1 < NCH) {
            int d0 = (ch + 1) * 16;
            #pragma unroll
            for (int i = 0; i < 4; i++)
                pa[i] = xb[(d0 + a_k + 4 * i) * HW_ + n0 + a_t];
            pb = *(const float4*)(Win + (size_t)(c0 + b_c) * D_ + d0 + b_k4 * 4);
        }
        #pragma unroll
        for (int kk = 0; kk < 16; kk++) {
            float4 av = *(const float4*)(&As[buf][kk][ty * 4]);
            float4 bv = *(const float4*)(&Bs[buf][kk][tx * 4]);
            float a[4] = {av.x, av.y, av.z, av.w};
            float b[4] = {bv.x, bv.y, bv.z, bv.w};
            #pragma unroll
            for (int i = 0; i < 4; i++)
                #pragma unroll
                for (int j = 0; j < 4; j++) acc[i][j] += a[i] * b[j];
        }
        if (ch + 1 < NCH) {
            int ob = buf ^ 1;
            #pragma unroll
            for (int i = 0; i < 4; i++) As[ob][a_k + 4 * i][a_t] = pa[i];
            Bs[ob][b_k4 * 4 + 0][b_c] = pb.x; Bs[ob][b_k4 * 4 + 1][b_c] = pb.y;
            Bs[ob][b_k4 * 4 + 2][b_c] = pb.z; Bs[ob][b_k4 * 4 + 3][b_c] = pb.w;
            __syncthreads();
        }
    }

    float4 bb = *(const float4*)(bin + c0 + tx * 4);
    float bv[4] = {bb.x, bb.y, bb.z, bb.w};
    #pragma unroll
    for (int i = 0; i < 4; i++) {
        float4 v;
        v.x = acc[i][0] + bv[0]; v.y = acc[i][1] + bv[1];
        v.z = acc[i][2] + bv[2]; v.w = acc[i][3] + bv[3];
        *(float4*)(g_z + (size_t)(t0 + ty * 4 + i) * CD_ + c0 + tx * 4) = v;
    }
}

// ---------------- fused distance GEMM + argmin ----------------
// Block: 128 tokens (Z tile persistent in smem, 128KB) x all 8192 codes,
// 64-code tiles, BK=16 double-buffered. Thread tile 8 tokens x 4 codes.
// score = cnorm[k] - 2 * (z . e_k); running per-thread (min,idx).
__global__ __launch_bounds__(256, 1)
void argmin_kernel(const float* __restrict__ E) {
    extern __shared__ float sm[];
    float* Zs = sm;                      // [256][128]
    float* Es = sm + 256 * 128;          // 2 x [16][64]

    int tid = threadIdx.x;
    int tx = tid & 15, ty = tid >> 4;
    int t0 = blockIdx.x * 128;

    // load Z tile transposed: Zs[c][t]
    for (int i = tid; i < 128 * CD_ / 4; i += 256) {   // 8192 float4
        int t  = i >> 6;
        int c4 = i & 63;
        float4 v = *(const float4*)(g_z + (size_t)(t0 + t) * CD_ + c4 * 4);
        Zs[(c4 * 4 + 0) * 128 + t] = v.x;
        Zs[(c4 * 4 + 1) * 128 + t] = v.y;
        Zs[(c4 * 4 + 2) * 128 + t] = v.z;
        Zs[(c4 * 4 + 3) * 128 + t] = v.w;
    }

    float bestV[8]; int bestI[8];
    #pragma unroll
    for (int i = 0; i < 8; i++) { bestV[i] = 3.402823466e38f; bestI[i] = 0; }
    float acc[8][4];
    #pragma unroll
    for (int i = 0; i < 8; i++)
        #pragma unroll
        for (int j = 0; j < 4; j++) acc[i][j] = 0.f;

    int code_l = tid >> 2;   // 0..63
    int c4     = tid & 3;

    // prefetch chunk 0 (code tile 0, c-dims 0..15)
    float4 pf = *(const float4*)(E + (size_t)code_l * CD_ + c4 * 4);
    __syncthreads();                       // Zs visible
    {
        float* Eb = Es;
        Eb[(c4 * 4 + 0) * 64 + code_l] = pf.x;
        Eb[(c4 * 4 + 1) * 64 + code_l] = pf.y;
        Eb[(c4 * 4 + 2) * 64 + code_l] = pf.z;
        Eb[(c4 * 4 + 3) * 64 + code_l] = pf.w;
    }
    __syncthreads();

    const int NCH = (K_ / 64) * (CD_ / 16);   // 2048 chunks
    #pragma unroll 1
    for (int ch = 0; ch < NCH; ch++) {
        int buf = ch & 1;
        float4 nxt;
        if (ch + 1 < NCH) {
            int nk = (ch + 1) >> 4;
            int nc = (ch + 1) & 15;
            nxt = *(const float4*)(E + (size_t)(nk * 64 + code_l) * CD_ + nc * 16 + c4 * 4);
        }
        const float* Eb = Es + buf * 16 * 64;
        int crow = (ch & 15) * 16;
        #pragma unroll
        for (int kk = 0; kk < 16; kk++) {
            float4 a0 = *(const float4*)(Zs + (crow + kk) * 128 + ty * 8);
            float4 a1 = *(const float4*)(Zs + (crow + kk) * 128 + ty * 8 + 4);
            float4 bvv = *(const float4*)(Eb + kk * 64 + tx * 4);
            float a[8] = {a0.x, a0.y, a0.z, a0.w, a1.x, a1.y, a1.z, a1.w};
            float b[4] = {bvv.x, bvv.y, bvv.z, bvv.w};
            #pragma unroll
            for (int i = 0; i < 8; i++)
                #pragma unroll
                for (int j = 0; j < 4; j++) acc[i][j] += a[i] * b[j];
        }
        if ((ch & 15) == 15) {
            int kt = ch >> 4;
            float4 cn = *(const float4*)(g_cnorm + kt * 64 + tx * 4);
            float cnv[4] = {cn.x, cn.y, cn.z, cn.w};
            #pragma unroll
            for (int i = 0; i < 8; i++) {
                #pragma unroll
                for (int j = 0; j < 4; j++) {
                    float s = cnv[j] - 2.0f * acc[i][j];
                    int k = kt * 64 + tx * 4 + j;
                    if (s < bestV[i]) { bestV[i] = s; bestI[i] = k; }
                    acc[i][j] = 0.f;
                }
            }
        }
        if (ch + 1 < NCH) {
            float* Eo = Es + (buf ^ 1) * 16 * 64;
            Eo[(c4 * 4 + 0) * 64 + code_l] = nxt.x;
            Eo[(c4 * 4 + 1) * 64 + code_l] = nxt.y;
            Eo[(c4 * 4 + 2) * 64 + code_l] = nxt.z;
            Eo[(c4 * 4 + 3) * 64 + code_l] = nxt.w;
            __syncthreads();
        }
    }

    // reduce across tx (same-ty = half-warp, width 16); ties -> lower index
    #pragma unroll
    for (int i = 0; i < 8; i++) {
        float v = bestV[i]; int bi = bestI[i];
        #pragma unroll
        for (int off = 8; off; off >>= 1) {
            float ov = __shfl_down_sync(0xffffffffu, v, off, 16);
            int   oi = __shfl_down_sync(0xffffffffu, bi, off, 16);
            if (ov < v || (ov == v && oi < bi)) { v = ov; bi = oi; }
        }
        if (tx == 0) g_idx[t0 + ty * 8 + i] = bi;
    }
}

// ---------------- GEMM2: out = q @ W_out^T + b_out, transposed store ----------------
__global__ __launch_bounds__(256, 2)
void proj_out_kernel(const float* __restrict__ E,
                     const float* __restrict__ Wout,
                     const float* __restrict__ bout,
                     float* __restrict__ out) {
    __shared__ float As[2][16][64];
    __shared__ float Bs[2][16][64];
    __shared__ int sIdx[64];
    int tid = threadIdx.x;
    int tx = tid & 15, ty = tid >> 4;
    int t0 = blockIdx.x * 64, c0 = blockIdx.y * 64;   // c0 = output-dim tile
    if (tid < 64) sIdx[tid] = g_idx[t0 + tid];
    __syncthreads();

    int a_t = tid >> 2, a_k4 = tid & 3;
    int b_c = tid >> 2, b_k4 = tid & 3;
    size_t rowA = (size_t)sIdx[a_t] * CD_;

    float acc[4][4];
    #pragma unroll
    for (int i = 0; i < 4; i++)
        #pragma unroll
        for (int j = 0; j < 4; j++) acc[i][j] = 0.f;

    float4 pa = *(const float4*)(E + rowA + a_k4 * 4);
    float4 pb = *(const float4*)(Wout + (size_t)(c0 + b_c) * CD_ + b_k4 * 4);
    As[0][a_k4 * 4 + 0][a_t] = pa.x; As[0][a_k4 * 4 + 1][a_t] = pa.y;
    As[0][a_k4 * 4 + 2][a_t] = pa.z; As[0][a_k4 * 4 + 3][a_t] = pa.w;
    Bs[0][b_k4 * 4 + 0][b_c] = pb.x; Bs[0][b_k4 * 4 + 1][b_c] = pb.y;
    Bs[0][b_k4 * 4 + 2][b_c] = pb.z; Bs[0][b_k4 * 4 + 3][b_c] = pb.w;
    __syncthreads();

    const int NCH = CD_ / 16;  // 16
    #pragma unroll 1
    for (int ch = 0; ch < NCH; ch++) {
        int buf = ch & 1;
        if (ch + 1 < NCH) {
            int k0 = (ch + 1) * 16;
            pa = *(const float4*)(E + rowA + k0 + a_k4 * 4);
            pb = *(const float4*)(Wout + (size_t)(c0 + b_c) * CD_ + k0 + b_k4 * 4);
        }
        #pragma unroll
        for (int kk = 0; kk < 16; kk++) {
            float4 av = *(const float4*)(&As[buf][kk][ty * 4]);
            float4 bv = *(const float4*)(&Bs[buf][kk][tx * 4]);
            float a[4] = {av.x, av.y, av.z, av.w};
            float b[4] = {bv.x, bv.y, bv.z, bv.w};
            #pragma unroll
            for (int i = 0; i < 4; i++)
                #pragma unroll
                for (int j = 0; j < 4; j++) acc[i][j] += a[i] * b[j];
        }
        if (ch + 1 < NCH) {
            int ob = buf ^ 1;
            As[ob][a_k4 * 4 + 0][a_t] = pa.x; As[ob][a_k4 * 4 + 1][a_t] = pa.y;
            As[ob][a_k4 * 4 + 2][a_t] = pa.z; As[ob][a_k4 * 4 + 3][a_t] = pa.w;
            Bs[ob][b_k4 * 4 + 0][b_c] = pb.x; Bs[ob][b_k4 * 4 + 1][b_c] = pb.y;
            Bs[ob][b_k4 * 4 + 2][b_c] = pb.z; Bs[ob][b_k4 * 4 + 3][b_c] = pb.w;
            __syncthreads();
        }
    }

    int batch = t0 >> 10;
    int n0 = t0 & 1023;
    float* ob = out + (size_t)batch * (D_ * HW_);
    #pragma unroll
    for (int j = 0; j < 4; j++) {
        int dcol = c0 + tx * 4 + j;
        float bo = bout[dcol];
        float4 v;
        v.x = acc[0][j] + bo; v.y = acc[1][j] + bo;
        v.z = acc[2][j] + bo; v.w = acc[3][j] + bo;
        *(float4*)(ob + (size_t)dcol * HW_ + n0 + ty * 4) = v;
    }
}

// ---------------- commitment loss ----------------
__global__ void loss_kernel(const float* __restrict__ E) {
    __shared__ float red[256];
    int tid = threadIdx.x;
    float s = 0.f;
    int stride = gridDim.x * blockDim.x;
    for (int e = blockIdx.x * blockDim.x + tid; e < NTOK * CD_; e += stride) {
        int t = e >> 8;
        float d = E[(size_t)g_idx[t] * CD_ + (e & 255)] - g_z[e];
        s += d * d;
    }
    red[tid] = s; __syncthreads();
    for (int o = 128; o; o >>= 1) {
        if (tid < o) red[tid] += red[tid + o];
        __syncthreads();
    }
    if (tid == 0) atomicAdd(&g_loss, (double)red[0]);
}

__global__ void finalize_kernel(float* __restrict__ out, int writeIdx, int writeLoss) {
    int i = blockIdx.x * blockDim.x + threadIdx.x;
    if (writeIdx && i < NTOK) out[OUT_N + i] = (float)g_idx[i];
    if (writeLoss && i == 0)
        out[OUT_N + NTOK] = (float)(g_loss * (1.0 / (double)(NTOK * CD_)));
}

// ---------------- launch ----------------
extern "C" void kernel_launch(void* const* d_in, const int* in_sizes, int n_in,
                              void* d_out, int out_size) {
    const float* x    = (const float*)d_in[0];
    const float* Win  = (const float*)d_in[1];
    const float* bin  = (const float*)d_in[2];
    const float* Wout = (const float*)d_in[3];
    const float* bout = (const float*)d_in[4];
    const float* cb   = (const float*)d_in[5];
    float* out = (float*)d_out;

    const int ARGMIN_SMEM = (256 * 128 + 2 * 16 * 64) * 4;  // 139264 B
    cudaFuncSetAttribute(argmin_kernel,
                         cudaFuncAttributeMaxDynamicSharedMemorySize, ARGMIN_SMEM);

    zero_loss_kernel<<<1, 1>>>();
    cnorm_kernel<<<K_ / 8, 256>>>(cb);

    dim3 g1(NTOK / 64, CD_ / 64);
    proj_in_kernel<<<g1, 256>>>(x, Win, bin);

    argmin_kernel<<<NTOK / 128, 256, ARGMIN_SMEM>>>(cb);

    dim3 g2(NTOK / 64, D_ / 64);
    proj_out_kernel<<<g2, 256>>>(cb, Wout, bout, out);

    loss_kernel<<<256, 256>>>(cb);

    int writeIdx  = (out_size >= OUT_N + NTOK) ? 1 : 0;
    int writeLoss = (out_size >= OUT_N + NTOK + 1) ? 1 : 0;
    finalize_kernel<<<(NTOK + 255) / 256, 256>>>(out, writeIdx, writeLoss);
}

// round 5
// speedup vs baseline: 1.1748x; 1.1746x over previous
#include <cuda_runtime.h>
#include <cuda_fp16.h>
#include <cstdint>

#define B_    16
#define D_    512
#define HW_   1024
#define CD_   256
#define K_    8192
#define NTOK  (B_ * HW_)
#define OUT_N (B_ * D_ * HW_)
#define TAU   1e-2f

// ---------------- scratch ----------------
__device__ float  g_z[NTOK * CD_];
__device__ __half g_zh[NTOK * CD_];
__device__ __half g_eh[K_ * CD_];
__device__ float  g_cnorm[K_];
__device__ int    g_idx[NTOK];
__device__ int    g_flags[NTOK];
__device__ int    g_flag_count;
__device__ double g_loss;

// ---------------- helpers ----------------
__device__ __forceinline__ uint32_t smem_u32(const void* p) {
    uint32_t a;
    asm("{ .reg .u64 t; cvta.to.shared.u64 t, %1; cvt.u32.u64 %0, t; }" : "=r"(a) : "l"(p));
    return a;
}
#define CP_ASYNC16(dst, src) \
    asm volatile("cp.async.cg.shared.global [%0], [%1], 16;" :: "r"(dst), "l"(src))
#define CP_COMMIT() asm volatile("cp.async.commit_group;" ::: "memory")

__device__ __forceinline__ void ldsm4(uint32_t& r0, uint32_t& r1, uint32_t& r2, uint32_t& r3,
                                      uint32_t addr) {
    asm volatile("ldmatrix.sync.aligned.m8n8.x4.shared.b16 {%0,%1,%2,%3}, [%4];"
                 : "=r"(r0), "=r"(r1), "=r"(r2), "=r"(r3) : "r"(addr));
}
__device__ __forceinline__ void hmma(float* c, uint32_t a0, uint32_t a1, uint32_t a2, uint32_t a3,
                                     uint32_t b0, uint32_t b1) {
    asm volatile(
        "mma.sync.aligned.m16n8k16.row.col.f32.f16.f16.f32 "
        "{%0,%1,%2,%3}, {%4,%5,%6,%7}, {%8,%9}, {%0,%1,%2,%3};"
        : "+f"(c[0]), "+f"(c[1]), "+f"(c[2]), "+f"(c[3])
        : "r"(a0), "r"(a1), "r"(a2), "r"(a3), "r"(b0), "r"(b1));
}

// smem layout (bytes): A [128][264]h = 67584 | B 2x[64][264]h = 67584 | cnorm 32768
#define LDA_B   528
#define SM_A    0
#define SM_B    67584
#define B_BUF   33792
#define SM_CN   135168
#define SM_TOT  167936

// ---------------- prep: cnorm + eh ----------------
__global__ void prep_codebook_kernel(const float* __restrict__ E) {
    int warp = (blockIdx.x * blockDim.x + threadIdx.x) >> 5;
    int lane = threadIdx.x & 31;
    if (warp >= K_) return;
    const float4* row = (const float4*)(E + (size_t)warp * CD_);
    float4 a = row[lane * 2], b = row[lane * 2 + 1];
    float v[8] = {a.x, a.y, a.z, a.w, b.x, b.y, b.z, b.w};
    float s = 0.f;
    __half h[8];
    #pragma unroll
    for (int i = 0; i < 8; i++) { s += v[i] * v[i]; h[i] = __float2half(v[i]); }
    *(uint4*)(g_eh + (size_t)warp * CD_ + lane * 8) = *(uint4*)h;
    #pragma unroll
    for (int o = 16; o; o >>= 1) s += __shfl_down_sync(0xffffffffu, s, o);
    if (lane == 0) g_cnorm[warp] = s;
}

__global__ void zero_kernel() { g_loss = 0.0; g_flag_count = 0; }

// ---------------- GEMM1: z = x^T W_in^T + b_in (+ fp16 copy) ----------------
__global__ __launch_bounds__(256, 2)
void proj_in_kernel(const float* __restrict__ x,
                    const float* __restrict__ Win,
                    const float* __restrict__ bin) {
    __shared__ float As[2][16][64];
    __shared__ float Bs[2][16][64];
    int tid = threadIdx.x;
    int tx = tid & 15, ty = tid >> 4;
    int t0 = blockIdx.x * 64, c0 = blockIdx.y * 64;
    int batch = t0 >> 10, n0 = t0 & 1023;
    const float* xb = x + (size_t)batch * (D_ * HW_);

    float acc[4][4];
    #pragma unroll
    for (int i = 0; i < 4; i++)
        #pragma unroll
        for (int j = 0; j < 4; j++) acc[i][j] = 0.f;

    int a_t = tid & 63, a_k = tid >> 6;
    int b_c = tid >> 2, b_k4 = tid & 3;
    float pa[4]; float4 pb;
    #pragma unroll
    for (int i = 0; i < 4; i++) pa[i] = xb[(a_k + 4 * i) * HW_ + n0 + a_t];
    pb = *(const float4*)(Win + (size_t)(c0 + b_c) * D_ + b_k4 * 4);
    #pragma unroll
    for (int i = 0; i < 4; i++) As[0][a_k + 4 * i][a_t] = pa[i];
    Bs[0][b_k4 * 4 + 0][b_c] = pb.x; Bs[0][b_k4 * 4 + 1][b_c] = pb.y;
    Bs[0][b_k4 * 4 + 2][b_c] = pb.z; Bs[0][b_k4 * 4 + 3][b_c] = pb.w;
    __syncthreads();

    #pragma unroll 1
    for (int ch = 0; ch < D_ / 16; ch++) {
        int buf = ch & 1;
        if (ch + 1 < D_ / 16) {
            int d0 = (ch + 1) * 16;
            #pragma unroll
            for (int i = 0; i < 4; i++) pa[i] = xb[(d0 + a_k + 4 * i) * HW_ + n0 + a_t];
            pb = *(const float4*)(Win + (size_t)(c0 + b_c) * D_ + d0 + b_k4 * 4);
        }
        #pragma unroll
        for (int kk = 0; kk < 16; kk++) {
            float4 av = *(const float4*)(&As[buf][kk][ty * 4]);
            float4 bv = *(const float4*)(&Bs[buf][kk][tx * 4]);
            float a[4] = {av.x, av.y, av.z, av.w};
            float b[4] = {bv.x, bv.y, bv.z, bv.w};
            #pragma unroll
            for (int i = 0; i < 4; i++)
                #pragma unroll
                for (int j = 0; j < 4; j++) acc[i][j] += a[i] * b[j];
        }
        if (ch + 1 < D_ / 16) {
            int ob = buf ^ 1;
            #pragma unroll
            for (int i = 0; i < 4; i++) As[ob][a_k + 4 * i][a_t] = pa[i];
            Bs[ob][b_k4 * 4 + 0][b_c] = pb.x; Bs[ob][b_k4 * 4 + 1][b_c] = pb.y;
            Bs[ob][b_k4 * 4 + 2][b_c] = pb.z; Bs[ob][b_k4 * 4 + 3][b_c] = pb.w;
            __syncthreads();
        }
    }

    float4 bb = *(const float4*)(bin + c0 + tx * 4);
    float bv[4] = {bb.x, bb.y, bb.z, bb.w};
    #pragma unroll
    for (int i = 0; i < 4; i++) {
        size_t row = (size_t)(t0 + ty * 4 + i);
        float4 v;
        v.x = acc[i][0] + bv[0]; v.y = acc[i][1] + bv[1];
        v.z = acc[i][2] + bv[2]; v.w = acc[i][3] + bv[3];
        *(float4*)(g_z + row * CD_ + c0 + tx * 4) = v;
        __half h[4] = {__float2half(v.x), __float2half(v.y),
                       __float2half(v.z), __float2half(v.w)};
        *(uint2*)(g_zh + row * CD_ + c0 + tx * 4) = *(uint2*)h;
    }
}

// ---------------- HMMA argmin ----------------
// 128 CTAs x 256 thr (8 warps). zh[128][256] resident in smem (row pad 264h).
// Stream 64-code tiles (128 tiles), double-buffered cp.async.
// Warp w owns tokens w*16..+15; acc = 8 n-frags (n=64). score = cnorm - 2*dot.
__global__ __launch_bounds__(256, 1)
void argmin_hmma_kernel() {
    extern __shared__ char smem[];
    const uint32_t su = smem_u32(smem);
    float* sCN = (float*)(smem + SM_CN);
    const int tid = threadIdx.x;
    const int w = tid >> 5, l = tid & 31;
    const int t0 = blockIdx.x * 128;

    // fill A (zh) rows, padded
    #pragma unroll
    for (int p = 0; p < 16; p++) {
        int idx = tid + p * 256;             // 4096 uint4
        int row = idx >> 5, ch = idx & 31;
        uint4 v = *(const uint4*)(g_zh + (size_t)(t0 + row) * CD_ + ch * 8);
        *(uint4*)(smem + SM_A + row * LDA_B + ch * 16) = v;
    }
    // cnorm -> smem
    #pragma unroll
    for (int p = 0; p < 8; p++) {
        int idx = tid + p * 256;             // 2048 uint4
        ((uint4*)sCN)[idx] = ((const uint4*)g_cnorm)[idx];
    }

    // prefetch B tile 0
    {
        const char* src = (const char*)g_eh;
        #pragma unroll
        for (int p = 0; p < 8; p++) {
            int idx = tid + p * 256;         // 2048 chunks of 16B
            int row = idx >> 5, ch = idx & 31;
            CP_ASYNC16(su + SM_B + row * LDA_B + ch * 16, src + row * 512 + ch * 16);
        }
        CP_COMMIT();
    }

    // lane-fixed ldmatrix addresses
    const uint32_t aAddr = su + SM_A + (w * 16 + (l & 7) + ((l >> 3) & 1) * 8) * LDA_B
                         + (l >> 4) * 16;
    const uint32_t bOff  = ((l >> 4) * 8 + (l & 7)) * LDA_B + ((l >> 3) & 1) * 16;

    float bestA = 3.4e38f, best2A = 3.4e38f; int idxA = 0;
    float bestB = 3.4e38f, best2B = 3.4e38f; int idxB = 0;

    #pragma unroll 1
    for (int t = 0; t < K_ / 64; t++) {
        if (t + 1 < K_ / 64) {
            const char* src = (const char*)(g_eh + (size_t)(t + 1) * 64 * CD_);
            uint32_t dst = su + SM_B + ((t + 1) & 1) * B_BUF;
            #pragma unroll
            for (int p = 0; p < 8; p++) {
                int idx = tid + p * 256;
                int row = idx >> 5, ch = idx & 31;
                CP_ASYNC16(dst + row * LDA_B + ch * 16, src + row * 512 + ch * 16);
            }
            CP_COMMIT();
            asm volatile("cp.async.wait_group 1;" ::: "memory");
        } else {
            asm volatile("cp.async.wait_group 0;" ::: "memory");
        }
        __syncthreads();

        const uint32_t bBase = su + SM_B + (t & 1) * B_BUF + bOff;
        float acc[32];
        #pragma unroll
        for (int i = 0; i < 32; i++) acc[i] = 0.f;

        #pragma unroll 4
        for (int k = 0; k < 16; k++) {
            uint32_t a0, a1, a2, a3;
            ldsm4(a0, a1, a2, a3, aAddr + k * 32);
            #pragma unroll
            for (int nb = 0; nb < 4; nb++) {
                uint32_t b0, b1, b2, b3;
                ldsm4(b0, b1, b2, b3, bBase + nb * (16 * LDA_B) + k * 32);
                hmma(acc + nb * 8,     a0, a1, a2, a3, b0, b1);
                hmma(acc + nb * 8 + 4, a0, a1, a2, a3, b2, b3);
            }
        }
        __syncthreads();

        // epilogue: scores + top-2  (frags: nb*8+q -> n-block 2*nb+(q>=4))
        #pragma unroll
        for (int j = 0; j < 8; j++) {
            float* c = acc + (j >> 1) * 8 + (j & 1) * 4;
            int c0 = t * 64 + j * 8 + (l & 3) * 2;
            float s0 = sCN[c0]     - 2.f * c[0];
            float s1 = sCN[c0 + 1] - 2.f * c[1];
            float s2 = sCN[c0]     - 2.f * c[2];
            float s3 = sCN[c0 + 1] - 2.f * c[3];
            if (s0 < bestA) { best2A = bestA; bestA = s0; idxA = c0; }
            else if (s0 < best2A) best2A = s0;
            if (s1 < bestA) { best2A = bestA; bestA = s1; idxA = c0 + 1; }
            else if (s1 < best2A) best2A = s1;
            if (s2 < bestB) { best2B = bestB; bestB = s2; idxB = c0; }
            else if (s2 < best2B) best2B = s2;
            if (s3 < bestB) { best2B = bestB; bestB = s3; idxB = c0 + 1; }
            else if (s3 < best2B) best2B = s3;
        }
    }

    // reduce across the 4 lanes sharing each token row
    #pragma unroll
    for (int d = 1; d < 4; d <<= 1) {
        float ob  = __shfl_xor_sync(~0u, bestA, d);
        float ob2 = __shfl_xor_sync(~0u, best2A, d);
        int   oi  = __shfl_xor_sync(~0u, idxA, d);
        if (ob < bestA || (ob == bestA && oi < idxA)) {
            best2A = fminf(bestA, ob2); bestA = ob; idxA = oi;
        } else best2A = fminf(best2A, ob);
        ob  = __shfl_xor_sync(~0u, bestB, d);
        ob2 = __shfl_xor_sync(~0u, best2B, d);
        oi  = __shfl_xor_sync(~0u, idxB, d);
        if (ob < bestB || (ob == bestB && oi < idxB)) {
            best2B = fminf(bestB, ob2); bestB = ob; idxB = oi;
        } else best2B = fminf(best2B, ob);
    }
    if ((l & 3) == 0) {
        int tokA = t0 + w * 16 + (l >> 2);
        int tokB = tokA + 8;
        g_idx[tokA] = idxA;
        g_idx[tokB] = idxB;
        if (best2A - bestA < TAU) g_flags[atomicAdd(&g_flag_count, 1)] = tokA;
        if (best2B - bestB < TAU) g_flags[atomicAdd(&g_flag_count, 1)] = tokB;
    }
}

// ---------------- exact fp32 rescan (batched, 4 tokens/CTA) ----------------
__global__ __launch_bounds__(256, 1)
void fallback_kernel(const float* __restrict__ E) {
    __shared__ float zs[4][260];
    __shared__ float sb[8][4];
    __shared__ int   si[8][4];
    __shared__ int   stok[4];
    int tid = threadIdx.x, w = tid >> 5, l = tid & 31;
    int cnt = g_flag_count;
    for (int base = blockIdx.x * 4; base < cnt; base += gridDim.x * 4) {
        int nt = cnt - base; if (nt > 4) nt = 4;
        if (tid < nt) stok[tid] = g_flags[base + tid];
        __syncthreads();
        for (int idx = tid; idx < nt * 64; idx += 256) {
            int row = idx >> 6, c4 = idx & 63;
            float4 v = *(const float4*)(g_z + (size_t)stok[row] * CD_ + c4 * 4);
            *(float4*)&zs[row][c4 * 4] = v;
        }
        __syncthreads();
        int tk = l >> 3, s = l & 7;
        bool act = tk < nt;
        float best = 3.4e38f; int bi = 0;
        for (int it = 0; it < 128; it++) {
            int code = it * 64 + w * 8 + s;
            const float4* er = (const float4*)(E + (size_t)code * CD_);
            float dot = 0.f;
            #pragma unroll 16
            for (int c4 = 0; c4 < 64; c4++) {
                float4 e4 = er[c4];
                float4 z4 = *(const float4*)&zs[tk][c4 * 4];
                dot += z4.x * e4.x + z4.y * e4.y + z4.z * e4.z + z4.w * e4.w;
            }
            float sc = g_cnorm[code] - 2.f * dot;
            if (act && sc < best) { best = sc; bi = code; }
        }
        #pragma unroll
        for (int d = 1; d < 8; d <<= 1) {
            float ob = __shfl_xor_sync(~0u, best, d);
            int   oi = __shfl_xor_sync(~0u, bi, d);
            if (ob < best || (ob == best && oi < bi)) { best = ob; bi = oi; }
        }
        if (s == 0 && act) { sb[w][tk] = best; si[w][tk] = bi; }
        __syncthreads();
        if (tid < nt) {
            float b = sb[0][tid]; int bi2 = si[0][tid];
            #pragma unroll
            for (int ww = 1; ww < 8; ww++) {
                if (sb[ww][tid] < b || (sb[ww][tid] == b && si[ww][tid] < bi2)) {
                    b = sb[ww][tid]; bi2 = si[ww][tid];
                }
            }
            g_idx[stok[tid]] = bi2;
        }
        __syncthreads();
    }
}

// ---------------- GEMM2: out = q W_out^T + b_out ----------------
__global__ __launch_bounds__(256, 2)
void proj_out_kernel(const float* __restrict__ E,
                     const float* __restrict__ Wout,
                     const float* __restrict__ bout,
                     float* __restrict__ out) {
    __shared__ float As[2][16][64];
    __shared__ float Bs[2][16][64];
    __shared__ int sIdx[64];
    int tid = threadIdx.x;
    int tx = tid & 15, ty = tid >> 4;
    int t0 = blockIdx.x * 64, c0 = blockIdx.y * 64;
    if (tid < 64) sIdx[tid] = g_idx[t0 + tid];
    __syncthreads();

    int a_t = tid >> 2, a_k4 = tid & 3;
    int b_c = tid >> 2, b_k4 = tid & 3;
    size_t rowA = (size_t)sIdx[a_t] * CD_;

    float acc[4][4];
    #pragma unroll
    for (int i = 0; i < 4; i++)
        #pragma unroll
        for (int j = 0; j < 4; j++) acc[i][j] = 0.f;

    float4 pa = *(const float4*)(E + rowA + a_k4 * 4);
    float4 pb = *(const float4*)(Wout + (size_t)(c0 + b_c) * CD_ + b_k4 * 4);
    As[0][a_k4 * 4 + 0][a_t] = pa.x; As[0][a_k4 * 4 + 1][a_t] = pa.y;
    As[0][a_k4 * 4 + 2][a_t] = pa.z; As[0][a_k4 * 4 + 3][a_t] = pa.w;
    Bs[0][b_k4 * 4 + 0][b_c] = pb.x; Bs[0][b_k4 * 4 + 1][b_c] = pb.y;
    Bs[0][b_k4 * 4 + 2][b_c] = pb.z; Bs[0][b_k4 * 4 + 3][b_c] = pb.w;
    __syncthreads();

    #pragma unroll 1
    for (int ch = 0; ch < CD_ / 16; ch++) {
        int buf = ch & 1;
        if (ch + 1 < CD_ / 16) {
            int k0 = (ch + 1) * 16;
            pa = *(const float4*)(E + rowA + k0 + a_k4 * 4);
            pb = *(const float4*)(Wout + (size_t)(c0 + b_c) * CD_ + k0 + b_k4 * 4);
        }
        #pragma unroll
        for (int kk = 0; kk < 16; kk++) {
            float4 av = *(const float4*)(&As[buf][kk][ty * 4]);
            float4 bv = *(const float4*)(&Bs[buf][kk][tx * 4]);
            float a[4] = {av.x, av.y, av.z, av.w};
            float b[4] = {bv.x, bv.y, bv.z, bv.w};
            #pragma unroll
            for (int i = 0; i < 4; i++)
                #pragma unroll
                for (int j = 0; j < 4; j++) acc[i][j] += a[i] * b[j];
        }
        if (ch + 1 < CD_ / 16) {
            int ob = buf ^ 1;
            As[ob][a_k4 * 4 + 0][a_t] = pa.x; As[ob][a_k4 * 4 + 1][a_t] = pa.y;
            As[ob][a_k4 * 4 + 2][a_t] = pa.z; As[ob][a_k4 * 4 + 3][a_t] = pa.w;
            Bs[ob][b_k4 * 4 + 0][b_c] = pb.x; Bs[ob][b_k4 * 4 + 1][b_c] = pb.y;
            Bs[ob][b_k4 * 4 + 2][b_c] = pb.z; Bs[ob][b_k4 * 4 + 3][b_c] = pb.w;
            __syncthreads();
        }
    }

    int batch = t0 >> 10, n0 = t0 & 1023;
    float* ob = out + (size_t)batch * (D_ * HW_);
    #pragma unroll
    for (int j = 0; j < 4; j++) {
        int dcol = c0 + tx * 4 + j;
        float bo = bout[dcol];
        float4 v;
        v.x = acc[0][j] + bo; v.y = acc[1][j] + bo;
        v.z = acc[2][j] + bo; v.w = acc[3][j] + bo;
        *(float4*)(ob + (size_t)dcol * HW_ + n0 + ty * 4) = v;
    }
}

// ---------------- loss + finalize ----------------
__global__ void loss_kernel(const float* __restrict__ E) {
    __shared__ float red[256];
    int tid = threadIdx.x;
    float s = 0.f;
    int stride = gridDim.x * blockDim.x;
    for (int e = blockIdx.x * blockDim.x + tid; e < NTOK * CD_; e += stride) {
        int t = e >> 8;
        float d = E[(size_t)g_idx[t] * CD_ + (e & 255)] - g_z[e];
        s += d * d;
    }
    red[tid] = s; __syncthreads();
    for (int o = 128; o; o >>= 1) {
        if (tid < o) red[tid] += red[tid + o];
        __syncthreads();
    }
    if (tid == 0) atomicAdd(&g_loss, (double)red[0]);
}

__global__ void finalize_kernel(float* __restrict__ out, int writeIdx, int writeLoss) {
    int i = blockIdx.x * blockDim.x + threadIdx.x;
    if (writeIdx && i < NTOK) out[OUT_N + i] = (float)g_idx[i];
    if (writeLoss && i == 0)
        out[OUT_N + NTOK] = (float)(g_loss * (1.0 / (double)(NTOK * CD_)));
}

// ---------------- launch ----------------
extern "C" void kernel_launch(void* const* d_in, const int* in_sizes, int n_in,
                              void* d_out, int out_size) {
    const float* x    = (const float*)d_in[0];
    const float* Win  = (const float*)d_in[1];
    const float* bin  = (const float*)d_in[2];
    const float* Wout = (const float*)d_in[3];
    const float* bout = (const float*)d_in[4];
    const float* cb   = (const float*)d_in[5];
    float* out = (float*)d_out;

    cudaFuncSetAttribute(argmin_hmma_kernel,
                         cudaFuncAttributeMaxDynamicSharedMemorySize, SM_TOT);

    zero_kernel<<<1, 1>>>();
    prep_codebook_kernel<<<K_ / 8, 256>>>(cb);

    dim3 g1(NTOK / 64, CD_ / 64);
    proj_in_kernel<<<g1, 256>>>(x, Win, bin);

    argmin_hmma_kernel<<<NTOK / 128, 256, SM_TOT>>>();
    fallback_kernel<<<256, 256>>>(cb);

    dim3 g2(NTOK / 64, D_ / 64);
    proj_out_kernel<<<g2, 256>>>(cb, Wout, bout, out);

    loss_kernel<<<256, 256>>>(cb);

    int writeIdx  = (out_size >= OUT_N + NTOK) ? 1 : 0;
    int writeLoss = (out_size >= OUT_N + NTOK + 1) ? 1 : 0;
    finalize_kernel<<<(NTOK + 255) / 256, 256>>>(out, writeIdx, writeLoss);
}

// round 6
// speedup vs baseline: 1.7919x; 1.5253x over previous
#include <cuda_runtime.h>
#include <cuda_fp16.h>
#include <cstdint>

#define B_    16
#define D_    512
#define HW_   1024
#define CD_   256
#define K_    8192
#define NTOK  (B_ * HW_)
#define OUT_N (B_ * D_ * HW_)
#define TAU   1e-2f

// ---------------- scratch ----------------
__device__ float  g_z[NTOK * CD_];
__device__ __half g_zh[NTOK * CD_];
__device__ __half g_eh[K_ * CD_];
__device__ float  g_cnorm[K_];
__device__ int    g_idx[NTOK];
__device__ int    g_flags[NTOK];
__device__ int    g_flag_count;
__device__ double g_loss;

// ---------------- helpers ----------------
__device__ __forceinline__ uint32_t smem_u32(const void* p) {
    uint32_t a;
    asm("{ .reg .u64 t; cvta.to.shared.u64 t, %1; cvt.u32.u64 %0, t; }" : "=r"(a) : "l"(p));
    return a;
}
#define CP_ASYNC16(dst, src) \
    asm volatile("cp.async.cg.shared.global [%0], [%1], 16;" :: "r"(dst), "l"(src))
#define CP_COMMIT() asm volatile("cp.async.commit_group;" ::: "memory")

__device__ __forceinline__ void ldsm4(uint32_t& r0, uint32_t& r1, uint32_t& r2, uint32_t& r3,
                                      uint32_t addr) {
    asm volatile("ldmatrix.sync.aligned.m8n8.x4.shared.b16 {%0,%1,%2,%3}, [%4];"
                 : "=r"(r0), "=r"(r1), "=r"(r2), "=r"(r3) : "r"(addr));
}
__device__ __forceinline__ void hmma(float* c, uint32_t a0, uint32_t a1, uint32_t a2, uint32_t a3,
                                     uint32_t b0, uint32_t b1) {
    asm volatile(
        "mma.sync.aligned.m16n8k16.row.col.f32.f16.f16.f32 "
        "{%0,%1,%2,%3}, {%4,%5,%6,%7}, {%8,%9}, {%0,%1,%2,%3};"
        : "+f"(c[0]), "+f"(c[1]), "+f"(c[2]), "+f"(c[3])
        : "r"(a0), "r"(a1), "r"(a2), "r"(a3), "r"(b0), "r"(b1));
}

// argmin smem layout (bytes): A [128][264]h | B 2x[64][264]h | cnorm
#define LDA_B   528
#define SM_A    0
#define SM_B    67584
#define B_BUF   33792
#define SM_CN   135168
#define SM_TOT  167936

// ---------------- prep: cnorm + eh ----------------
__global__ void prep_codebook_kernel(const float* __restrict__ E) {
    int warp = (blockIdx.x * blockDim.x + threadIdx.x) >> 5;
    int lane = threadIdx.x & 31;
    if (warp >= K_) return;
    const float4* row = (const float4*)(E + (size_t)warp * CD_);
    float4 a = row[lane * 2], b = row[lane * 2 + 1];
    float v[8] = {a.x, a.y, a.z, a.w, b.x, b.y, b.z, b.w};
    float s = 0.f;
    __half h[8];
    #pragma unroll
    for (int i = 0; i < 8; i++) { s += v[i] * v[i]; h[i] = __float2half(v[i]); }
    *(uint4*)(g_eh + (size_t)warp * CD_ + lane * 8) = *(uint4*)h;
    #pragma unroll
    for (int o = 16; o; o >>= 1) s += __shfl_down_sync(0xffffffffu, s, o);
    if (lane == 0) g_cnorm[warp] = s;
}

__global__ void zero_kernel() { g_loss = 0.0; g_flag_count = 0; }

// ---------------- GEMM1: z = x^T W_in^T + b_in (+ fp16 copy) ----------------
__global__ __launch_bounds__(256, 2)
void proj_in_kernel(const float* __restrict__ x,
                    const float* __restrict__ Win,
                    const float* __restrict__ bin) {
    __shared__ float As[2][16][64];
    __shared__ float Bs[2][16][64];
    int tid = threadIdx.x;
    int tx = tid & 15, ty = tid >> 4;
    int t0 = blockIdx.x * 64, c0 = blockIdx.y * 64;
    int batch = t0 >> 10, n0 = t0 & 1023;
    const float* xb = x + (size_t)batch * (D_ * HW_);

    float acc[4][4];
    #pragma unroll
    for (int i = 0; i < 4; i++)
        #pragma unroll
        for (int j = 0; j < 4; j++) acc[i][j] = 0.f;

    int a_t = tid & 63, a_k = tid >> 6;
    int b_c = tid >> 2, b_k4 = tid & 3;
    float pa[4]; float4 pb;
    #pragma unroll
    for (int i = 0; i < 4; i++) pa[i] = xb[(a_k + 4 * i) * HW_ + n0 + a_t];
    pb = *(const float4*)(Win + (size_t)(c0 + b_c) * D_ + b_k4 * 4);
    #pragma unroll
    for (int i = 0; i < 4; i++) As[0][a_k + 4 * i][a_t] = pa[i];
    Bs[0][b_k4 * 4 + 0][b_c] = pb.x; Bs[0][b_k4 * 4 + 1][b_c] = pb.y;
    Bs[0][b_k4 * 4 + 2][b_c] = pb.z; Bs[0][b_k4 * 4 + 3][b_c] = pb.w;
    __syncthreads();

    #pragma unroll 1
    for (int ch = 0; ch < D_ / 16; ch++) {
        int buf = ch & 1;
        if (ch + 1 < D_ / 16) {
            int d0 = (ch + 1) * 16;
            #pragma unroll
            for (int i = 0; i < 4; i++) pa[i] = xb[(d0 + a_k + 4 * i) * HW_ + n0 + a_t];
            pb = *(const float4*)(Win + (size_t)(c0 + b_c) * D_ + d0 + b_k4 * 4);
        }
        #pragma unroll
        for (int kk = 0; kk < 16; kk++) {
            float4 av = *(const float4*)(&As[buf][kk][ty * 4]);
            float4 bv = *(const float4*)(&Bs[buf][kk][tx * 4]);
            float a[4] = {av.x, av.y, av.z, av.w};
            float b[4] = {bv.x, bv.y, bv.z, bv.w};
            #pragma unroll
            for (int i = 0; i < 4; i++)
                #pragma unroll
                for (int j = 0; j < 4; j++) acc[i][j] += a[i] * b[j];
        }
        if (ch + 1 < D_ / 16) {
            int ob = buf ^ 1;
            #pragma unroll
            for (int i = 0; i < 4; i++) As[ob][a_k + 4 * i][a_t] = pa[i];
            Bs[ob][b_k4 * 4 + 0][b_c] = pb.x; Bs[ob][b_k4 * 4 + 1][b_c] = pb.y;
            Bs[ob][b_k4 * 4 + 2][b_c] = pb.z; Bs[ob][b_k4 * 4 + 3][b_c] = pb.w;
            __syncthreads();
        }
    }

    float4 bb = *(const float4*)(bin + c0 + tx * 4);
    float bv[4] = {bb.x, bb.y, bb.z, bb.w};
    #pragma unroll
    for (int i = 0; i < 4; i++) {
        size_t row = (size_t)(t0 + ty * 4 + i);
        float4 v;
        v.x = acc[i][0] + bv[0]; v.y = acc[i][1] + bv[1];
        v.z = acc[i][2] + bv[2]; v.w = acc[i][3] + bv[3];
        *(float4*)(g_z + row * CD_ + c0 + tx * 4) = v;
        __half h[4] = {__float2half(v.x), __float2half(v.y),
                       __float2half(v.z), __float2half(v.w)};
        *(uint2*)(g_zh + row * CD_ + c0 + tx * 4) = *(uint2*)h;
    }
}

// ---------------- HMMA argmin (unchanged from round 5) ----------------
__global__ __launch_bounds__(256, 1)
void argmin_hmma_kernel() {
    extern __shared__ char smem[];
    const uint32_t su = smem_u32(smem);
    float* sCN = (float*)(smem + SM_CN);
    const int tid = threadIdx.x;
    const int w = tid >> 5, l = tid & 31;
    const int t0 = blockIdx.x * 128;

    #pragma unroll
    for (int p = 0; p < 16; p++) {
        int idx = tid + p * 256;
        int row = idx >> 5, ch = idx & 31;
        uint4 v = *(const uint4*)(g_zh + (size_t)(t0 + row) * CD_ + ch * 8);
        *(uint4*)(smem + SM_A + row * LDA_B + ch * 16) = v;
    }
    #pragma unroll
    for (int p = 0; p < 8; p++) {
        int idx = tid + p * 256;
        ((uint4*)sCN)[idx] = ((const uint4*)g_cnorm)[idx];
    }

    {
        const char* src = (const char*)g_eh;
        #pragma unroll
        for (int p = 0; p < 8; p++) {
            int idx = tid + p * 256;
            int row = idx >> 5, ch = idx & 31;
            CP_ASYNC16(su + SM_B + row * LDA_B + ch * 16, src + row * 512 + ch * 16);
        }
        CP_COMMIT();
    }

    const uint32_t aAddr = su + SM_A + (w * 16 + (l & 7) + ((l >> 3) & 1) * 8) * LDA_B
                         + (l >> 4) * 16;
    const uint32_t bOff  = ((l >> 4) * 8 + (l & 7)) * LDA_B + ((l >> 3) & 1) * 16;

    float bestA = 3.4e38f, best2A = 3.4e38f; int idxA = 0;
    float bestB = 3.4e38f, best2B = 3.4e38f; int idxB = 0;

    #pragma unroll 1
    for (int t = 0; t < K_ / 64; t++) {
        if (t + 1 < K_ / 64) {
            const char* src = (const char*)(g_eh + (size_t)(t + 1) * 64 * CD_);
            uint32_t dst = su + SM_B + ((t + 1) & 1) * B_BUF;
            #pragma unroll
            for (int p = 0; p < 8; p++) {
                int idx = tid + p * 256;
                int row = idx >> 5, ch = idx & 31;
                CP_ASYNC16(dst + row * LDA_B + ch * 16, src + row * 512 + ch * 16);
            }
            CP_COMMIT();
            asm volatile("cp.async.wait_group 1;" ::: "memory");
        } else {
            asm volatile("cp.async.wait_group 0;" ::: "memory");
        }
        __syncthreads();

        const uint32_t bBase = su + SM_B + (t & 1) * B_BUF + bOff;
        float acc[32];
        #pragma unroll
        for (int i = 0; i < 32; i++) acc[i] = 0.f;

        #pragma unroll 4
        for (int k = 0; k < 16; k++) {
            uint32_t a0, a1, a2, a3;
            ldsm4(a0, a1, a2, a3, aAddr + k * 32);
            #pragma unroll
            for (int nb = 0; nb < 4; nb++) {
                uint32_t b0, b1, b2, b3;
                ldsm4(b0, b1, b2, b3, bBase + nb * (16 * LDA_B) + k * 32);
                hmma(acc + nb * 8,     a0, a1, a2, a3, b0, b1);
                hmma(acc + nb * 8 + 4, a0, a1, a2, a3, b2, b3);
            }
        }
        __syncthreads();

        #pragma unroll
        for (int j = 0; j < 8; j++) {
            float* c = acc + (j >> 1) * 8 + (j & 1) * 4;
            int c0 = t * 64 + j * 8 + (l & 3) * 2;
            float s0 = sCN[c0]     - 2.f * c[0];
            float s1 = sCN[c0 + 1] - 2.f * c[1];
            float s2 = sCN[c0]     - 2.f * c[2];
            float s3 = sCN[c0 + 1] - 2.f * c[3];
            if (s0 < bestA) { best2A = bestA; bestA = s0; idxA = c0; }
            else if (s0 < best2A) best2A = s0;
            if (s1 < bestA) { best2A = bestA; bestA = s1; idxA = c0 + 1; }
            else if (s1 < best2A) best2A = s1;
            if (s2 < bestB) { best2B = bestB; bestB = s2; idxB = c0; }
            else if (s2 < best2B) best2B = s2;
            if (s3 < bestB) { best2B = bestB; bestB = s3; idxB = c0 + 1; }
            else if (s3 < best2B) best2B = s3;
        }
    }

    #pragma unroll
    for (int d = 1; d < 4; d <<= 1) {
        float ob  = __shfl_xor_sync(~0u, bestA, d);
        float ob2 = __shfl_xor_sync(~0u, best2A, d);
        int   oi  = __shfl_xor_sync(~0u, idxA, d);
        if (ob < bestA || (ob == bestA && oi < idxA)) {
            best2A = fminf(bestA, ob2); bestA = ob; idxA = oi;
        } else best2A = fminf(best2A, ob);
        ob  = __shfl_xor_sync(~0u, bestB, d);
        ob2 = __shfl_xor_sync(~0u, best2B, d);
        oi  = __shfl_xor_sync(~0u, idxB, d);
        if (ob < bestB || (ob == bestB && oi < idxB)) {
            best2B = fminf(bestB, ob2); bestB = ob; idxB = oi;
        } else best2B = fminf(best2B, ob);
    }
    if ((l & 3) == 0) {
        int tokA = t0 + w * 16 + (l >> 2);
        int tokB = tokA + 8;
        g_idx[tokA] = idxA;
        g_idx[tokB] = idxB;
        if (best2A - bestA < TAU) g_flags[atomicAdd(&g_flag_count, 1)] = tokA;
        if (best2B - bestB < TAU) g_flags[atomicAdd(&g_flag_count, 1)] = tokB;
    }
}

// ---------------- exact fp32 rescan v2: warp-per-token, smem-tiled codebook ----
// 8 tokens/CTA. Codebook streamed in 32-code tiles (32KB) double-buffered via
// cp.async, stored with additive chunk swizzle (c4+row)&63 -> conflict-free LDS.
// Lane owns one code per tile; z row broadcast from smem.
#define FB_TOK 8
#define FB_TILE_F (32 * 256)                 /* floats per tile */
__global__ __launch_bounds__(256, 1)
void fallback_kernel(const float* __restrict__ E) {
    extern __shared__ float fsm[];           // 2 tiles: 65536 B
    __shared__ float zs[FB_TOK][264];
    __shared__ int   stok[FB_TOK];
    const uint32_t su = smem_u32(fsm);
    int tid = threadIdx.x, w = tid >> 5, l = tid & 31;
    int cnt = g_flag_count;

    for (int base = blockIdx.x * FB_TOK; base < cnt; base += gridDim.x * FB_TOK) {
        int nt = cnt - base; if (nt > FB_TOK) nt = FB_TOK;
        __syncthreads();
        if (tid < nt) stok[tid] = g_flags[base + tid];
        __syncthreads();
        for (int i = tid; i < nt * 64; i += 256) {
            int r = i >> 6, c4 = i & 63;
            *(float4*)&zs[r][c4 * 4] =
                *(const float4*)(g_z + (size_t)stok[r] * CD_ + c4 * 4);
        }

        // prefetch tile 0
        #pragma unroll
        for (int p = 0; p < 8; p++) {
            int i = tid + p * 256;           // 2048 chunks
            int r = i >> 6, c4 = i & 63;
            uint32_t dst = su + (uint32_t)((r * 256 + (((c4 + r) & 63) << 2)) << 2);
            CP_ASYNC16(dst, (const char*)(E + (size_t)r * CD_) + c4 * 16);
        }
        CP_COMMIT();

        float best = 3.4e38f; int bi = 0;
        const float* zrow = zs[w < nt ? w : 0];

        #pragma unroll 1
        for (int t = 0; t < K_ / 32; t++) {
            if (t + 1 < K_ / 32) {
                const float* src = E + (size_t)(t + 1) * 32 * CD_;
                uint32_t dstb = su + (uint32_t)((((t + 1) & 1) * FB_TILE_F) << 2);
                #pragma unroll
                for (int p = 0; p < 8; p++) {
                    int i = tid + p * 256;
                    int r = i >> 6, c4 = i & 63;
                    uint32_t dst = dstb + (uint32_t)((r * 256 + (((c4 + r) & 63) << 2)) << 2);
                    CP_ASYNC16(dst, (const char*)(src + (size_t)r * CD_) + c4 * 16);
                }
                CP_COMMIT();
                asm volatile("cp.async.wait_group 1;" ::: "memory");
            } else {
                asm volatile("cp.async.wait_group 0;" ::: "memory");
            }
            __syncthreads();

            const float* Eb = fsm + (t & 1) * FB_TILE_F + l * 256;
            float dot = 0.f;
            #pragma unroll 16
            for (int c4 = 0; c4 < 64; c4++) {
                float4 e4 = *(const float4*)(Eb + (((c4 + l) & 63) << 2));
                float4 z4 = *(const float4*)(zrow + c4 * 4);
                dot += z4.x * e4.x + z4.y * e4.y + z4.z * e4.z + z4.w * e4.w;
            }
            int code = t * 32 + l;
            float sc = __ldg(&g_cnorm[code]) - 2.f * dot;
            if (sc < best) { best = sc; bi = code; }
            __syncthreads();
        }

        // warp reduce: min score, ties -> lower index
        #pragma unroll
        for (int d = 1; d < 32; d <<= 1) {
            float ob = __shfl_xor_sync(~0u, best, d);
            int   oi = __shfl_xor_sync(~0u, bi, d);
            if (ob < best || (ob == best && oi < bi)) { best = ob; bi = oi; }
        }
        if (l == 0 && w < nt) g_idx[stok[w]] = bi;
    }
}

// ---------------- GEMM2: out = q W_out^T + b_out ----------------
__global__ __launch_bounds__(256, 2)
void proj_out_kernel(const float* __restrict__ E,
                     const float* __restrict__ Wout,
                     const float* __restrict__ bout,
                     float* __restrict__ out) {
    __shared__ float As[2][16][64];
    __shared__ float Bs[2][16][64];
    __shared__ int sIdx[64];
    int tid = threadIdx.x;
    int tx = tid & 15, ty = tid >> 4;
    int t0 = blockIdx.x * 64, c0 = blockIdx.y * 64;
    if (tid < 64) sIdx[tid] = g_idx[t0 + tid];
    __syncthreads();

    int a_t = tid >> 2, a_k4 = tid & 3;
    int b_c = tid >> 2, b_k4 = tid & 3;
    size_t rowA = (size_t)sIdx[a_t] * CD_;

    float acc[4][4];
    #pragma unroll
    for (int i = 0; i < 4; i++)
        #pragma unroll
        for (int j = 0; j < 4; j++) acc[i][j] = 0.f;

    float4 pa = *(const float4*)(E + rowA + a_k4 * 4);
    float4 pb = *(const float4*)(Wout + (size_t)(c0 + b_c) * CD_ + b_k4 * 4);
    As[0][a_k4 * 4 + 0][a_t] = pa.x; As[0][a_k4 * 4 + 1][a_t] = pa.y;
    As[0][a_k4 * 4 + 2][a_t] = pa.z; As[0][a_k4 * 4 + 3][a_t] = pa.w;
    Bs[0][b_k4 * 4 + 0][b_c] = pb.x; Bs[0][b_k4 * 4 + 1][b_c] = pb.y;
    Bs[0][b_k4 * 4 + 2][b_c] = pb.z; Bs[0][b_k4 * 4 + 3][b_c] = pb.w;
    __syncthreads();

    #pragma unroll 1
    for (int ch = 0; ch < CD_ / 16; ch++) {
        int buf = ch & 1;
        if (ch + 1 < CD_ / 16) {
            int k0 = (ch + 1) * 16;
            pa = *(const float4*)(E + rowA + k0 + a_k4 * 4);
            pb = *(const float4*)(Wout + (size_t)(c0 + b_c) * CD_ + k0 + b_k4 * 4);
        }
        #pragma unroll
        for (int kk = 0; kk < 16; kk++) {
            float4 av = *(const float4*)(&As[buf][kk][ty * 4]);
            float4 bv = *(const float4*)(&Bs[buf][kk][tx * 4]);
            float a[4] = {av.x, av.y, av.z, av.w};
            float b[4] = {bv.x, bv.y, bv.z, bv.w};
            #pragma unroll
            for (int i = 0; i < 4; i++)
                #pragma unroll
                for (int j = 0; j < 4; j++) acc[i][j] += a[i] * b[j];
        }
        if (ch + 1 < CD_ / 16) {
            int ob = buf ^ 1;
            As[ob][a_k4 * 4 + 0][a_t] = pa.x; As[ob][a_k4 * 4 + 1][a_t] = pa.y;
            As[ob][a_k4 * 4 + 2][a_t] = pa.z; As[ob][a_k4 * 4 + 3][a_t] = pa.w;
            Bs[ob][b_k4 * 4 + 0][b_c] = pb.x; Bs[ob][b_k4 * 4 + 1][b_c] = pb.y;
            Bs[ob][b_k4 * 4 + 2][b_c] = pb.z; Bs[ob][b_k4 * 4 + 3][b_c] = pb.w;
            __syncthreads();
        }
    }

    int batch = t0 >> 10, n0 = t0 & 1023;
    float* ob = out + (size_t)batch * (D_ * HW_);
    #pragma unroll
    for (int j = 0; j < 4; j++) {
        int dcol = c0 + tx * 4 + j;
        float bo = bout[dcol];
        float4 v;
        v.x = acc[0][j] + bo; v.y = acc[1][j] + bo;
        v.z = acc[2][j] + bo; v.w = acc[3][j] + bo;
        *(float4*)(ob + (size_t)dcol * HW_ + n0 + ty * 4) = v;
    }
}

// ---------------- loss + finalize ----------------
__global__ void loss_kernel(const float* __restrict__ E) {
    __shared__ float red[256];
    int tid = threadIdx.x;
    float s = 0.f;
    int stride = gridDim.x * blockDim.x;
    for (int e = blockIdx.x * blockDim.x + tid; e < NTOK * CD_; e += stride) {
        int t = e >> 8;
        float d = E[(size_t)g_idx[t] * CD_ + (e & 255)] - g_z[e];
        s += d * d;
    }
    red[tid] = s; __syncthreads();
    for (int o = 128; o; o >>= 1) {
        if (tid < o) red[tid] += red[tid + o];
        __syncthreads();
    }
    if (tid == 0) atomicAdd(&g_loss, (double)red[0]);
}

__global__ void finalize_kernel(float* __restrict__ out, int writeIdx, int writeLoss) {
    int i = blockIdx.x * blockDim.x + threadIdx.x;
    if (writeIdx && i < NTOK) out[OUT_N + i] = (float)g_idx[i];
    if (writeLoss && i == 0)
        out[OUT_N + NTOK] = (float)(g_loss * (1.0 / (double)(NTOK * CD_)));
}

// ---------------- launch ----------------
extern "C" void kernel_launch(void* const* d_in, const int* in_sizes, int n_in,
                              void* d_out, int out_size) {
    const float* x    = (const float*)d_in[0];
    const float* Win  = (const float*)d_in[1];
    const float* bin  = (const float*)d_in[2];
    const float* Wout = (const float*)d_in[3];
    const float* bout = (const float*)d_in[4];
    const float* cb   = (const float*)d_in[5];
    float* out = (float*)d_out;

    cudaFuncSetAttribute(argmin_hmma_kernel,
                         cudaFuncAttributeMaxDynamicSharedMemorySize, SM_TOT);
    cudaFuncSetAttribute(fallback_kernel,
                         cudaFuncAttributeMaxDynamicSharedMemorySize,
                         2 * FB_TILE_F * 4);

    zero_kernel<<<1, 1>>>();
    prep_codebook_kernel<<<K_ / 8, 256>>>(cb);

    dim3 g1(NTOK / 64, CD_ / 64);
    proj_in_kernel<<<g1, 256>>>(x, Win, bin);

    argmin_hmma_kernel<<<NTOK / 128, 256, SM_TOT>>>();
    fallback_kernel<<<128, 256, 2 * FB_TILE_F * 4>>>(cb);

    dim3 g2(NTOK / 64, D_ / 64);
    proj_out_kernel<<<g2, 256>>>(cb, Wout, bout, out);

    loss_kernel<<<256, 256>>>(cb);

    int writeIdx  = (out_size >= OUT_N + NTOK) ? 1 : 0;
    int writeLoss = (out_size >= OUT_N + NTOK + 1) ? 1 : 0;
    finalize_kernel<<<(NTOK + 255) / 256, 256>>>(out, writeIdx, writeLoss);
}

// round 9
// speedup vs baseline: 1.8768x; 1.0474x over previous
#include <cuda_runtime.h>
#include <cuda_fp16.h>
#include <cstdint>

#define B_    16
#define D_    512
#define HW_   1024
#define CD_   256
#define K_    8192
#define NTOK  (B_ * HW_)
#define OUT_N (B_ * D_ * HW_)
#define TAU   1e-2f

// ---------------- scratch ----------------
__device__ float  g_z[NTOK * CD_];
__device__ __half g_zh[NTOK * CD_];
__device__ __half g_eh[K_ * CD_];
__device__ float  g_wq[K_ * D_];
__device__ float  g_cnorm[K_];
__device__ int    g_idx[NTOK];
__device__ int    g_flags[NTOK];
__device__ int    g_flag_count;
__device__ double g_loss;

// ---------------- helpers ----------------
__device__ __forceinline__ uint32_t smem_u32(const void* p) {
    uint32_t a;
    asm("{ .reg .u64 t; cvta.to.shared.u64 t, %1; cvt.u32.u64 %0, t; }" : "=r"(a) : "l"(p));
    return a;
}
#define CP_ASYNC16(dst, src) \
    asm volatile("cp.async.cg.shared.global [%0], [%1], 16;" :: "r"(dst), "l"(src))
#define CP_COMMIT() asm volatile("cp.async.commit_group;" ::: "memory")

__device__ __forceinline__ void ldsm4(uint32_t& r0, uint32_t& r1, uint32_t& r2, uint32_t& r3,
                                      uint32_t addr) {
    asm volatile("ldmatrix.sync.aligned.m8n8.x4.shared.b16 {%0,%1,%2,%3}, [%4];"
                 : "=r"(r0), "=r"(r1), "=r"(r2), "=r"(r3) : "r"(addr));
}
__device__ __forceinline__ void hmma(float* c, uint32_t a0, uint32_t a1, uint32_t a2, uint32_t a3,
                                     uint32_t b0, uint32_t b1) {
    asm volatile(
        "mma.sync.aligned.m16n8k16.row.col.f32.f16.f16.f32 "
        "{%0,%1,%2,%3}, {%4,%5,%6,%7}, {%8,%9}, {%0,%1,%2,%3};"
        : "+f"(c[0]), "+f"(c[1]), "+f"(c[2]), "+f"(c[3])
        : "r"(a0), "r"(a1), "r"(a2), "r"(a3), "r"(b0), "r"(b1));
}

// argmin smem layout (bytes): A [128][264]h | B 2x[64][264]h | cnorm
#define LDA_B   528
#define SM_A    0
#define SM_B    67584
#define B_BUF   33792
#define SM_CN   135168
#define SM_TOT  167936

// ---------------- prep: cnorm + eh ----------------
__global__ void prep_codebook_kernel(const float* __restrict__ E) {
    int warp = (blockIdx.x * blockDim.x + threadIdx.x) >> 5;
    int lane = threadIdx.x & 31;
    if (warp >= K_) return;
    const float4* row = (const float4*)(E + (size_t)warp * CD_);
    float4 a = row[lane * 2], b = row[lane * 2 + 1];
    float v[8] = {a.x, a.y, a.z, a.w, b.x, b.y, b.z, b.w};
    float s = 0.f;
    __half h[8];
    #pragma unroll
    for (int i = 0; i < 8; i++) { s += v[i] * v[i]; h[i] = __float2half(v[i]); }
    *(uint4*)(g_eh + (size_t)warp * CD_ + lane * 8) = *(uint4*)h;
    #pragma unroll
    for (int o = 16; o; o >>= 1) s += __shfl_down_sync(0xffffffffu, s, o);
    if (lane == 0) g_cnorm[warp] = s;
}

__global__ void zero_kernel() { g_loss = 0.0; g_flag_count = 0; }

// ---------------- GEMM1: z = x^T W_in^T + b_in (+ fp16 copy) [proven] ----------------
__global__ __launch_bounds__(256, 2)
void proj_in_kernel(const float* __restrict__ x,
                    const float* __restrict__ Win,
                    const float* __restrict__ bin) {
    __shared__ float As[2][16][64];
    __shared__ float Bs[2][16][64];
    int tid = threadIdx.x;
    int tx = tid & 15, ty = tid >> 4;
    int t0 = blockIdx.x * 64, c0 = blockIdx.y * 64;
    int batch = t0 >> 10, n0 = t0 & 1023;
    const float* xb = x + (size_t)batch * (D_ * HW_);

    float acc[4][4];
    #pragma unroll
    for (int i = 0; i < 4; i++)
        #pragma unroll
        for (int j = 0; j < 4; j++) acc[i][j] = 0.f;

    int a_t = tid & 63, a_k = tid >> 6;
    int b_c = tid >> 2, b_k4 = tid & 3;
    float pa[4]; float4 pb;
    #pragma unroll
    for (int i = 0; i < 4; i++) pa[i] = xb[(a_k + 4 * i) * HW_ + n0 + a_t];
    pb = *(const float4*)(Win + (size_t)(c0 + b_c) * D_ + b_k4 * 4);
    #pragma unroll
    for (int i = 0; i < 4; i++) As[0][a_k + 4 * i][a_t] = pa[i];
    Bs[0][b_k4 * 4 + 0][b_c] = pb.x; Bs[0][b_k4 * 4 + 1][b_c] = pb.y;
    Bs[0][b_k4 * 4 + 2][b_c] = pb.z; Bs[0][b_k4 * 4 + 3][b_c] = pb.w;
    __syncthreads();

    #pragma unroll 1
    for (int ch = 0; ch < D_ / 16; ch++) {
        int buf = ch & 1;
        if (ch + 1 < D_ / 16) {
            int d0 = (ch + 1) * 16;
            #pragma unroll
            for (int i = 0; i < 4; i++) pa[i] = xb[(d0 + a_k + 4 * i) * HW_ + n0 + a_t];
            pb = *(const float4*)(Win + (size_t)(c0 + b_c) * D_ + d0 + b_k4 * 4);
        }
        #pragma unroll
        for (int kk = 0; kk < 16; kk++) {
            float4 av = *(const float4*)(&As[buf][kk][ty * 4]);
            float4 bv = *(const float4*)(&Bs[buf][kk][tx * 4]);
            float a[4] = {av.x, av.y, av.z, av.w};
            float b[4] = {bv.x, bv.y, bv.z, bv.w};
            #pragma unroll
            for (int i = 0; i < 4; i++)
                #pragma unroll
                for (int j = 0; j < 4; j++) acc[i][j] += a[i] * b[j];
        }
        if (ch + 1 < D_ / 16) {
            int ob = buf ^ 1;
            #pragma unroll
            for (int i = 0; i < 4; i++) As[ob][a_k + 4 * i][a_t] = pa[i];
            Bs[ob][b_k4 * 4 + 0][b_c] = pb.x; Bs[ob][b_k4 * 4 + 1][b_c] = pb.y;
            Bs[ob][b_k4 * 4 + 2][b_c] = pb.z; Bs[ob][b_k4 * 4 + 3][b_c] = pb.w;
            __syncthreads();
        }
    }

    float4 bb = *(const float4*)(bin + c0 + tx * 4);
    float bv[4] = {bb.x, bb.y, bb.z, bb.w};
    #pragma unroll
    for (int i = 0; i < 4; i++) {
        size_t row = (size_t)(t0 + ty * 4 + i);
        float4 v;
        v.x = acc[i][0] + bv[0]; v.y = acc[i][1] + bv[1];
        v.z = acc[i][2] + bv[2]; v.w = acc[i][3] + bv[3];
        *(float4*)(g_z + row * CD_ + c0 + tx * 4) = v;
        __half h[4] = {__float2half(v.x), __float2half(v.y),
                       __float2half(v.z), __float2half(v.w)};
        *(uint2*)(g_zh + row * CD_ + c0 + tx * 4) = *(uint2*)h;
    }
}

// ---------------- Wq = E W_out^T  (minimal diff of proven proj_out) ----------------
// A rows = codebook rows directly; C row-major [K, D]; no bias (added in gather).
__global__ __launch_bounds__(256, 2)
void wq_kernel(const float* __restrict__ E,
               const float* __restrict__ Wout) {
    __shared__ float As[2][16][64];
    __shared__ float Bs[2][16][64];
    int tid = threadIdx.x;
    int tx = tid & 15, ty = tid >> 4;
    int t0 = blockIdx.x * 64, c0 = blockIdx.y * 64;   // t0 = code tile, c0 = d tile

    int a_t = tid >> 2, a_k4 = tid & 3;
    int b_c = tid >> 2, b_k4 = tid & 3;
    size_t rowA = (size_t)(t0 + a_t) * CD_;

    float acc[4][4];
    #pragma unroll
    for (int i = 0; i < 4; i++)
        #pragma unroll
        for (int j = 0; j < 4; j++) acc[i][j] = 0.f;

    float4 pa = *(const float4*)(E + rowA + a_k4 * 4);
    float4 pb = *(const float4*)(Wout + (size_t)(c0 + b_c) * CD_ + b_k4 * 4);
    As[0][a_k4 * 4 + 0][a_t] = pa.x; As[0][a_k4 * 4 + 1][a_t] = pa.y;
    As[0][a_k4 * 4 + 2][a_t] = pa.z; As[0][a_k4 * 4 + 3][a_t] = pa.w;
    Bs[0][b_k4 * 4 + 0][b_c] = pb.x; Bs[0][b_k4 * 4 + 1][b_c] = pb.y;
    Bs[0][b_k4 * 4 + 2][b_c] = pb.z; Bs[0][b_k4 * 4 + 3][b_c] = pb.w;
    __syncthreads();

    #pragma unroll 1
    for (int ch = 0; ch < CD_ / 16; ch++) {
        int buf = ch & 1;
        if (ch + 1 < CD_ / 16) {
            int k0 = (ch + 1) * 16;
            pa = *(const float4*)(E + rowA + k0 + a_k4 * 4);
            pb = *(const float4*)(Wout + (size_t)(c0 + b_c) * CD_ + k0 + b_k4 * 4);
        }
        #pragma unroll
        for (int kk = 0; kk < 16; kk++) {
            float4 av = *(const float4*)(&As[buf][kk][ty * 4]);
            float4 bv = *(const float4*)(&Bs[buf][kk][tx * 4]);
            float a[4] = {av.x, av.y, av.z, av.w};
            float b[4] = {bv.x, bv.y, bv.z, bv.w};
            #pragma unroll
            for (int i = 0; i < 4; i++)
                #pragma unroll
                for (int j = 0; j < 4; j++) acc[i][j] += a[i] * b[j];
        }
        if (ch + 1 < CD_ / 16) {
            int ob = buf ^ 1;
            As[ob][a_k4 * 4 + 0][a_t] = pa.x; As[ob][a_k4 * 4 + 1][a_t] = pa.y;
            As[ob][a_k4 * 4 + 2][a_t] = pa.z; As[ob][a_k4 * 4 + 3][a_t] = pa.w;
            Bs[ob][b_k4 * 4 + 0][b_c] = pb.x; Bs[ob][b_k4 * 4 + 1][b_c] = pb.y;
            Bs[ob][b_k4 * 4 + 2][b_c] = pb.z; Bs[ob][b_k4 * 4 + 3][b_c] = pb.w;
            __syncthreads();
        }
    }

    // acc[i][j] = Wq[t0 + ty*4 + i][c0 + tx*4 + j], store row-major
    #pragma unroll
    for (int i = 0; i < 4; i++) {
        float4 v;
        v.x = acc[i][0]; v.y = acc[i][1]; v.z = acc[i][2]; v.w = acc[i][3];
        *(float4*)(g_wq + (size_t)(t0 + ty * 4 + i) * D_ + c0 + tx * 4) = v;
    }
}

// ---------------- HMMA argmin (unchanged, proven) ----------------
__global__ __launch_bounds__(256, 1)
void argmin_hmma_kernel() {
    extern __shared__ char smem[];
    const uint32_t su = smem_u32(smem);
    float* sCN = (float*)(smem + SM_CN);
    const int tid = threadIdx.x;
    const int w = tid >> 5, l = tid & 31;
    const int t0 = blockIdx.x * 128;

    #pragma unroll
    for (int p = 0; p < 16; p++) {
        int idx = tid + p * 256;
        int row = idx >> 5, ch = idx & 31;
        uint4 v = *(const uint4*)(g_zh + (size_t)(t0 + row) * CD_ + ch * 8);
        *(uint4*)(smem + SM_A + row * LDA_B + ch * 16) = v;
    }
    #pragma unroll
    for (int p = 0; p < 8; p++) {
        int idx = tid + p * 256;
        ((uint4*)sCN)[idx] = ((const uint4*)g_cnorm)[idx];
    }
    {
        const char* src = (const char*)g_eh;
        #pragma unroll
        for (int p = 0; p < 8; p++) {
            int idx = tid + p * 256;
            int row = idx >> 5, ch = idx & 31;
            CP_ASYNC16(su + SM_B + row * LDA_B + ch * 16, src + row * 512 + ch * 16);
        }
        CP_COMMIT();
    }

    const uint32_t aAddr = su + SM_A + (w * 16 + (l & 7) + ((l >> 3) & 1) * 8) * LDA_B
                         + (l >> 4) * 16;
    const uint32_t bOff  = ((l >> 4) * 8 + (l & 7)) * LDA_B + ((l >> 3) & 1) * 16;

    float bestA = 3.4e38f, best2A = 3.4e38f; int idxA = 0;
    float bestB = 3.4e38f, best2B = 3.4e38f; int idxB = 0;

    #pragma unroll 1
    for (int t = 0; t < K_ / 64; t++) {
        if (t + 1 < K_ / 64) {
            const char* src = (const char*)(g_eh + (size_t)(t + 1) * 64 * CD_);
            uint32_t dst = su + SM_B + ((t + 1) & 1) * B_BUF;
            #pragma unroll
            for (int p = 0; p < 8; p++) {
                int idx = tid + p * 256;
                int row = idx >> 5, ch = idx & 31;
                CP_ASYNC16(dst + row * LDA_B + ch * 16, src + row * 512 + ch * 16);
            }
            CP_COMMIT();
            asm volatile("cp.async.wait_group 1;" ::: "memory");
        } else {
            asm volatile("cp.async.wait_group 0;" ::: "memory");
        }
        __syncthreads();

        const uint32_t bBase = su + SM_B + (t & 1) * B_BUF + bOff;
        float acc[32];
        #pragma unroll
        for (int i = 0; i < 32; i++) acc[i] = 0.f;

        #pragma unroll 4
        for (int k = 0; k < 16; k++) {
            uint32_t a0, a1, a2, a3;
            ldsm4(a0, a1, a2, a3, aAddr + k * 32);
            #pragma unroll
            for (int nb = 0; nb < 4; nb++) {
                uint32_t b0, b1, b2, b3;
                ldsm4(b0, b1, b2, b3, bBase + nb * (16 * LDA_B) + k * 32);
                hmma(acc + nb * 8,     a0, a1, a2, a3, b0, b1);
                hmma(acc + nb * 8 + 4, a0, a1, a2, a3, b2, b3);
            }
        }
        __syncthreads();

        #pragma unroll
        for (int j = 0; j < 8; j++) {
            float* c = acc + (j >> 1) * 8 + (j & 1) * 4;
            int c0 = t * 64 + j * 8 + (l & 3) * 2;
            float s0 = sCN[c0]     - 2.f * c[0];
            float s1 = sCN[c0 + 1] - 2.f * c[1];
            float s2 = sCN[c0]     - 2.f * c[2];
            float s3 = sCN[c0 + 1] - 2.f * c[3];
            if (s0 < bestA) { best2A = bestA; bestA = s0; idxA = c0; }
            else if (s0 < best2A) best2A = s0;
            if (s1 < bestA) { best2A = bestA; bestA = s1; idxA = c0 + 1; }
            else if (s1 < best2A) best2A = s1;
            if (s2 < bestB) { best2B = bestB; bestB = s2; idxB = c0; }
            else if (s2 < best2B) best2B = s2;
            if (s3 < bestB) { best2B = bestB; bestB = s3; idxB = c0 + 1; }
            else if (s3 < best2B) best2B = s3;
        }
    }

    #pragma unroll
    for (int d = 1; d < 4; d <<= 1) {
        float ob  = __shfl_xor_sync(~0u, bestA, d);
        float ob2 = __shfl_xor_sync(~0u, best2A, d);
        int   oi  = __shfl_xor_sync(~0u, idxA, d);
        if (ob < bestA || (ob == bestA && oi < idxA)) {
            best2A = fminf(bestA, ob2); bestA = ob; idxA = oi;
        } else best2A = fminf(best2A, ob);
        ob  = __shfl_xor_sync(~0u, bestB, d);
        ob2 = __shfl_xor_sync(~0u, best2B, d);
        oi  = __shfl_xor_sync(~0u, idxB, d);
        if (ob < bestB || (ob == bestB && oi < idxB)) {
            best2B = fminf(bestB, ob2); bestB = ob; idxB = oi;
        } else best2B = fminf(best2B, ob);
    }
    if ((l & 3) == 0) {
        int tokA = t0 + w * 16 + (l >> 2);
        int tokB = tokA + 8;
        g_idx[tokA] = idxA;
        g_idx[tokB] = idxB;
        if (best2A - bestA < TAU) g_flags[atomicAdd(&g_flag_count, 1)] = tokA;
        if (best2B - bestB < TAU) g_flags[atomicAdd(&g_flag_count, 1)] = tokB;
    }
}

// ---------------- exact fp32 rescan (unchanged, proven) ----------------
#define FB_TOK 8
#define FB_TILE_F (32 * 256)
__global__ __launch_bounds__(256, 1)
void fallback_kernel(const float* __restrict__ E) {
    extern __shared__ float fsm[];
    __shared__ float zs[FB_TOK][264];
    __shared__ int   stok[FB_TOK];
    const uint32_t su = smem_u32(fsm);
    int tid = threadIdx.x, w = tid >> 5, l = tid & 31;
    int cnt = g_flag_count;

    for (int base = blockIdx.x * FB_TOK; base < cnt; base += gridDim.x * FB_TOK) {
        int nt = cnt - base; if (nt > FB_TOK) nt = FB_TOK;
        __syncthreads();
        if (tid < nt) stok[tid] = g_flags[base + tid];
        __syncthreads();
        for (int i = tid; i < nt * 64; i += 256) {
            int r = i >> 6, c4 = i & 63;
            *(float4*)&zs[r][c4 * 4] =
                *(const float4*)(g_z + (size_t)stok[r] * CD_ + c4 * 4);
        }
        #pragma unroll
        for (int p = 0; p < 8; p++) {
            int i = tid + p * 256;
            int r = i >> 6, c4 = i & 63;
            uint32_t dst = su + (uint32_t)((r * 256 + (((c4 + r) & 63) << 2)) << 2);
            CP_ASYNC16(dst, (const char*)(E + (size_t)r * CD_) + c4 * 16);
        }
        CP_COMMIT();

        float best = 3.4e38f; int bi = 0;
        const float* zrow = zs[w < nt ? w : 0];

        #pragma unroll 1
        for (int t = 0; t < K_ / 32; t++) {
            if (t + 1 < K_ / 32) {
                const float* src = E + (size_t)(t + 1) * 32 * CD_;
                uint32_t dstb = su + (uint32_t)((((t + 1) & 1) * FB_TILE_F) << 2);
                #pragma unroll
                for (int p = 0; p < 8; p++) {
                    int i = tid + p * 256;
                    int r = i >> 6, c4 = i & 63;
                    uint32_t dst = dstb + (uint32_t)((r * 256 + (((c4 + r) & 63) << 2)) << 2);
                    CP_ASYNC16(dst, (const char*)(src + (size_t)r * CD_) + c4 * 16);
                }
                CP_COMMIT();
                asm volatile("cp.async.wait_group 1;" ::: "memory");
            } else {
                asm volatile("cp.async.wait_group 0;" ::: "memory");
            }
            __syncthreads();

            const float* Eb = fsm + (t & 1) * FB_TILE_F + l * 256;
            float dot = 0.f;
            #pragma unroll 16
            for (int c4 = 0; c4 < 64; c4++) {
                float4 e4 = *(const float4*)(Eb + (((c4 + l) & 63) << 2));
                float4 z4 = *(const float4*)(zrow + c4 * 4);
                dot += z4.x * e4.x + z4.y * e4.y + z4.z * e4.z + z4.w * e4.w;
            }
            int code = t * 32 + l;
            float sc = __ldg(&g_cnorm[code]) - 2.f * dot;
            if (sc < best) { best = sc; bi = code; }
            __syncthreads();
        }
        #pragma unroll
        for (int d = 1; d < 32; d <<= 1) {
            float ob = __shfl_xor_sync(~0u, best, d);
            int   oi = __shfl_xor_sync(~0u, bi, d);
            if (ob < best || (ob == best && oi < bi)) { best = ob; bi = oi; }
        }
        if (l == 0 && w < nt) g_idx[stok[w]] = bi;
    }
}

// ---------------- gather: out[b][d][n] = Wq[idx[t]][d] + bout[d] ----------------
// row pad 132 floats (528 B, 16B-aligned) -> float4 stores legal.
__global__ __launch_bounds__(256, 4)
void gather_out_kernel(const float* __restrict__ bout, float* __restrict__ out) {
    __shared__ float s[64][132];
    __shared__ int sidx[64];
    int nt = blockIdx.x, b = blockIdx.y;
    int tid = threadIdx.x, w = tid >> 5, l = tid & 31;
    int t0 = b * 1024 + nt * 64;
    if (tid < 64) sidx[tid] = g_idx[t0 + tid];
    __syncthreads();
    float* ob = out + (size_t)b * (D_ * HW_) + nt * 64;
    #pragma unroll 1
    for (int dc = 0; dc < 4; dc++) {
        int d0 = dc * 128;
        #pragma unroll
        for (int tk = 0; tk < 8; tk++) {
            int tok = w * 8 + tk;
            float4 v = *(const float4*)(g_wq + (size_t)sidx[tok] * D_ + d0 + l * 4);
            *(float4*)&s[tok][l * 4] = v;
        }
        __syncthreads();
        #pragma unroll
        for (int it = 0; it < 32; it++) {
            int idx = tid + it * 256;
            int d = idx >> 6, tok = idx & 63;
            ob[(size_t)(d0 + d) * HW_ + tok] = s[tok][d] + __ldg(bout + d0 + d);
        }
        __syncthreads();
    }
}

// ---------------- loss + finalize ----------------
__global__ void loss_kernel(const float* __restrict__ E) {
    __shared__ float red[256];
    int tid = threadIdx.x;
    float s = 0.f;
    int stride = gridDim.x * blockDim.x;
    for (int e = blockIdx.x * blockDim.x + tid; e < NTOK * CD_; e += stride) {
        int t = e >> 8;
        float d = E[(size_t)g_idx[t] * CD_ + (e & 255)] - g_z[e];
        s += d * d;
    }
    red[tid] = s; __syncthreads();
    for (int o = 128; o; o >>= 1) {
        if (tid < o) red[tid] += red[tid + o];
        __syncthreads();
    }
    if (tid == 0) atomicAdd(&g_loss, (double)red[0]);
}

__global__ void finalize_kernel(float* __restrict__ out, int writeIdx, int writeLoss) {
    int i = blockIdx.x * blockDim.x + threadIdx.x;
    if (writeIdx && i < NTOK) out[OUT_N + i] = (float)g_idx[i];
    if (writeLoss && i == 0)
        out[OUT_N + NTOK] = (float)(g_loss * (1.0 / (double)(NTOK * CD_)));
}

// ---------------- launch ----------------
extern "C" void kernel_launch(void* const* d_in, const int* in_sizes, int n_in,
                              void* d_out, int out_size) {
    const float* x    = (const float*)d_in[0];
    const float* Win  = (const float*)d_in[1];
    const float* bin  = (const float*)d_in[2];
    const float* Wout = (const float*)d_in[3];
    const float* bout = (const float*)d_in[4];
    const float* cb   = (const float*)d_in[5];
    float* out = (float*)d_out;

    cudaFuncSetAttribute(argmin_hmma_kernel,
                         cudaFuncAttributeMaxDynamicSharedMemorySize, SM_TOT);
    cudaFuncSetAttribute(fallback_kernel,
                         cudaFuncAttributeMaxDynamicSharedMemorySize,
                         2 * FB_TILE_F * 4);

    zero_kernel<<<1, 1>>>();
    prep_codebook_kernel<<<K_ / 8, 256>>>(cb);

    dim3 g1(NTOK / 64, CD_ / 64);
    proj_in_kernel<<<g1, 256>>>(x, Win, bin);

    dim3 gq(K_ / 64, D_ / 64);
    wq_kernel<<<gq, 256>>>(cb, Wout);

    argmin_hmma_kernel<<<NTOK / 128, 256, SM_TOT>>>();
    fallback_kernel<<<128, 256, 2 * FB_TILE_F * 4>>>(cb);

    gather_out_kernel<<<dim3(HW_ / 64, B_), 256>>>(bout, out);
    loss_kernel<<<256, 256>>>(cb);

    int writeIdx  = (out_size >= OUT_N + NTOK) ? 1 : 0;
    int writeLoss = (out_size >= OUT_N + NTOK + 1) ? 1 : 0;
    finalize_kernel<<<(NTOK + 255) / 256, 256>>>(out, writeIdx, writeLoss);
}

// round 10
// speedup vs baseline: 2.8425x; 1.5146x over previous
#include <cuda_runtime.h>
#include <cuda_fp16.h>
#include <cstdint>

#define B_    16
#define D_    512
#define HW_   1024
#define CD_   256
#define K_    8192
#define NTOK  (B_ * HW_)
#define OUT_N (B_ * D_ * HW_)
#define TAU   1e-2f

// ---------------- scratch ----------------
__device__ float  g_z[NTOK * CD_];
__device__ __half g_zh[NTOK * CD_];
__device__ __half g_eh[K_ * CD_];
__device__ float  g_wq[K_ * D_];
__device__ float  g_cnorm[K_];
__device__ int    g_idx[NTOK];
__device__ int    g_flags[NTOK];
__device__ int    g_flag_count;
__device__ unsigned long long g_fbkey[NTOK];
__device__ double g_loss;

// ---------------- helpers ----------------
__device__ __forceinline__ uint32_t smem_u32(const void* p) {
    uint32_t a;
    asm("{ .reg .u64 t; cvta.to.shared.u64 t, %1; cvt.u32.u64 %0, t; }" : "=r"(a) : "l"(p));
    return a;
}
#define CP_ASYNC16(dst, src) \
    asm volatile("cp.async.cg.shared.global [%0], [%1], 16;" :: "r"(dst), "l"(src))
#define CP_COMMIT() asm volatile("cp.async.commit_group;" ::: "memory")

__device__ __forceinline__ void ldsm4(uint32_t& r0, uint32_t& r1, uint32_t& r2, uint32_t& r3,
                                      uint32_t addr) {
    asm volatile("ldmatrix.sync.aligned.m8n8.x4.shared.b16 {%0,%1,%2,%3}, [%4];"
                 : "=r"(r0), "=r"(r1), "=r"(r2), "=r"(r3) : "r"(addr));
}
__device__ __forceinline__ void hmma(float* c, uint32_t a0, uint32_t a1, uint32_t a2, uint32_t a3,
                                     uint32_t b0, uint32_t b1) {
    asm volatile(
        "mma.sync.aligned.m16n8k16.row.col.f32.f16.f16.f32 "
        "{%0,%1,%2,%3}, {%4,%5,%6,%7}, {%8,%9}, {%0,%1,%2,%3};"
        : "+f"(c[0]), "+f"(c[1]), "+f"(c[2]), "+f"(c[3])
        : "r"(a0), "r"(a1), "r"(a2), "r"(a3), "r"(b0), "r"(b1));
}

// argmin smem layout (bytes): A [128][264]h | B 2x[64][264]h | cnorm
#define LDA_B   528
#define SM_A    0
#define SM_B    67584
#define B_BUF   33792
#define SM_CN   135168
#define SM_TOT  167936

// ---------------- prep: cnorm + eh ----------------
__global__ void prep_codebook_kernel(const float* __restrict__ E) {
    int warp = (blockIdx.x * blockDim.x + threadIdx.x) >> 5;
    int lane = threadIdx.x & 31;
    if (warp >= K_) return;
    const float4* row = (const float4*)(E + (size_t)warp * CD_);
    float4 a = row[lane * 2], b = row[lane * 2 + 1];
    float v[8] = {a.x, a.y, a.z, a.w, b.x, b.y, b.z, b.w};
    float s = 0.f;
    __half h[8];
    #pragma unroll
    for (int i = 0; i < 8; i++) { s += v[i] * v[i]; h[i] = __float2half(v[i]); }
    *(uint4*)(g_eh + (size_t)warp * CD_ + lane * 8) = *(uint4*)h;
    #pragma unroll
    for (int o = 16; o; o >>= 1) s += __shfl_down_sync(0xffffffffu, s, o);
    if (lane == 0) g_cnorm[warp] = s;
}

__global__ void zero_kernel() { g_loss = 0.0; g_flag_count = 0; }

__global__ void init_fb_kernel() {
    int i = blockIdx.x * blockDim.x + threadIdx.x;
    if (i < NTOK) g_fbkey[i] = 0xFFFFFFFFFFFFFFFFull;
}

// ---------------- GEMM1 v2: z = x^T W_in^T + b_in (+ fp16 copy) ----------------
// Tile 128(M) x 64(N), BK=16 double-buffered, thread tile 8x4.
__global__ __launch_bounds__(256, 2)
void proj_in_kernel(const float* __restrict__ x,
                    const float* __restrict__ Win,
                    const float* __restrict__ bin) {
    __shared__ float As[2][16][128];
    __shared__ float Bs[2][16][64];
    int tid = threadIdx.x;
    int tx = tid & 15, ty = tid >> 4;
    int t0 = blockIdx.x * 128, c0 = blockIdx.y * 64;
    int batch = t0 >> 10, n0 = t0 & 1023;
    const float* xb = x + (size_t)batch * (D_ * HW_);

    float acc[8][4];
    #pragma unroll
    for (int i = 0; i < 8; i++)
        #pragma unroll
        for (int j = 0; j < 4; j++) acc[i][j] = 0.f;

    int a_t = tid & 127, a_k2 = tid >> 7;   // token, k-base (0/1)
    int b_c = tid >> 2, b_k4 = tid & 3;
    float pa[8]; float4 pb;
    #pragma unroll
    for (int i = 0; i < 8; i++) pa[i] = xb[(a_k2 + 2 * i) * HW_ + n0 + a_t];
    pb = *(const float4*)(Win + (size_t)(c0 + b_c) * D_ + b_k4 * 4);
    #pragma unroll
    for (int i = 0; i < 8; i++) As[0][a_k2 + 2 * i][a_t] = pa[i];
    Bs[0][b_k4 * 4 + 0][b_c] = pb.x; Bs[0][b_k4 * 4 + 1][b_c] = pb.y;
    Bs[0][b_k4 * 4 + 2][b_c] = pb.z; Bs[0][b_k4 * 4 + 3][b_c] = pb.w;
    __syncthreads();

    #pragma unroll 1
    for (int ch = 0; ch < D_ / 16; ch++) {
        int buf = ch & 1;
        if (ch + 1 < D_ / 16) {
            int d0 = (ch + 1) * 16;
            #pragma unroll
            for (int i = 0; i < 8; i++)
                pa[i] = xb[(d0 + a_k2 + 2 * i) * HW_ + n0 + a_t];
            pb = *(const float4*)(Win + (size_t)(c0 + b_c) * D_ + d0 + b_k4 * 4);
        }
        #pragma unroll
        for (int kk = 0; kk < 16; kk++) {
            float4 a0 = *(const float4*)(&As[buf][kk][ty * 8]);
            float4 a1 = *(const float4*)(&As[buf][kk][ty * 8 + 4]);
            float4 bv = *(const float4*)(&Bs[buf][kk][tx * 4]);
            float a[8] = {a0.x, a0.y, a0.z, a0.w, a1.x, a1.y, a1.z, a1.w};
            float b[4] = {bv.x, bv.y, bv.z, bv.w};
            #pragma unroll
            for (int i = 0; i < 8; i++)
                #pragma unroll
                for (int j = 0; j < 4; j++) acc[i][j] += a[i] * b[j];
        }
        if (ch + 1 < D_ / 16) {
            int ob = buf ^ 1;
            #pragma unroll
            for (int i = 0; i < 8; i++) As[ob][a_k2 + 2 * i][a_t] = pa[i];
            Bs[ob][b_k4 * 4 + 0][b_c] = pb.x; Bs[ob][b_k4 * 4 + 1][b_c] = pb.y;
            Bs[ob][b_k4 * 4 + 2][b_c] = pb.z; Bs[ob][b_k4 * 4 + 3][b_c] = pb.w;
            __syncthreads();
        }
    }

    float4 bb = *(const float4*)(bin + c0 + tx * 4);
    float bv[4] = {bb.x, bb.y, bb.z, bb.w};
    #pragma unroll
    for (int i = 0; i < 8; i++) {
        size_t row = (size_t)(t0 + ty * 8 + i);
        float4 v;
        v.x = acc[i][0] + bv[0]; v.y = acc[i][1] + bv[1];
        v.z = acc[i][2] + bv[2]; v.w = acc[i][3] + bv[3];
        *(float4*)(g_z + row * CD_ + c0 + tx * 4) = v;
        __half h[4] = {__float2half(v.x), __float2half(v.y),
                       __float2half(v.z), __float2half(v.w)};
        *(uint2*)(g_zh + row * CD_ + c0 + tx * 4) = *(uint2*)h;
    }
}

// ---------------- Wq = E W_out^T (proven) ----------------
__global__ __launch_bounds__(256, 2)
void wq_kernel(const float* __restrict__ E,
               const float* __restrict__ Wout) {
    __shared__ float As[2][16][64];
    __shared__ float Bs[2][16][64];
    int tid = threadIdx.x;
    int tx = tid & 15, ty = tid >> 4;
    int t0 = blockIdx.x * 64, c0 = blockIdx.y * 64;

    int a_t = tid >> 2, a_k4 = tid & 3;
    int b_c = tid >> 2, b_k4 = tid & 3;
    size_t rowA = (size_t)(t0 + a_t) * CD_;

    float acc[4][4];
    #pragma unroll
    for (int i = 0; i < 4; i++)
        #pragma unroll
        for (int j = 0; j < 4; j++) acc[i][j] = 0.f;

    float4 pa = *(const float4*)(E + rowA + a_k4 * 4);
    float4 pb = *(const float4*)(Wout + (size_t)(c0 + b_c) * CD_ + b_k4 * 4);
    As[0][a_k4 * 4 + 0][a_t] = pa.x; As[0][a_k4 * 4 + 1][a_t] = pa.y;
    As[0][a_k4 * 4 + 2][a_t] = pa.z; As[0][a_k4 * 4 + 3][a_t] = pa.w;
    Bs[0][b_k4 * 4 + 0][b_c] = pb.x; Bs[0][b_k4 * 4 + 1][b_c] = pb.y;
    Bs[0][b_k4 * 4 + 2][b_c] = pb.z; Bs[0][b_k4 * 4 + 3][b_c] = pb.w;
    __syncthreads();

    #pragma unroll 1
    for (int ch = 0; ch < CD_ / 16; ch++) {
        int buf = ch & 1;
        if (ch + 1 < CD_ / 16) {
            int k0 = (ch + 1) * 16;
            pa = *(const float4*)(E + rowA + k0 + a_k4 * 4);
            pb = *(const float4*)(Wout + (size_t)(c0 + b_c) * CD_ + k0 + b_k4 * 4);
        }
        #pragma unroll
        for (int kk = 0; kk < 16; kk++) {
            float4 av = *(const float4*)(&As[buf][kk][ty * 4]);
            float4 bv = *(const float4*)(&Bs[buf][kk][tx * 4]);
            float a[4] = {av.x, av.y, av.z, av.w};
            float b[4] = {bv.x, bv.y, bv.z, bv.w};
            #pragma unroll
            for (int i = 0; i < 4; i++)
                #pragma unroll
                for (int j = 0; j < 4; j++) acc[i][j] += a[i] * b[j];
        }
        if (ch + 1 < CD_ / 16) {
            int ob = buf ^ 1;
            As[ob][a_k4 * 4 + 0][a_t] = pa.x; As[ob][a_k4 * 4 + 1][a_t] = pa.y;
            As[ob][a_k4 * 4 + 2][a_t] = pa.z; As[ob][a_k4 * 4 + 3][a_t] = pa.w;
            Bs[ob][b_k4 * 4 + 0][b_c] = pb.x; Bs[ob][b_k4 * 4 + 1][b_c] = pb.y;
            Bs[ob][b_k4 * 4 + 2][b_c] = pb.z; Bs[ob][b_k4 * 4 + 3][b_c] = pb.w;
            __syncthreads();
        }
    }

    #pragma unroll
    for (int i = 0; i < 4; i++) {
        float4 v;
        v.x = acc[i][0]; v.y = acc[i][1]; v.z = acc[i][2]; v.w = acc[i][3];
        *(float4*)(g_wq + (size_t)(t0 + ty * 4 + i) * D_ + c0 + tx * 4) = v;
    }
}

// ---------------- HMMA argmin (unchanged, proven) ----------------
__global__ __launch_bounds__(256, 1)
void argmin_hmma_kernel() {
    extern __shared__ char smem[];
    const uint32_t su = smem_u32(smem);
    float* sCN = (float*)(smem + SM_CN);
    const int tid = threadIdx.x;
    const int w = tid >> 5, l = tid & 31;
    const int t0 = blockIdx.x * 128;

    #pragma unroll
    for (int p = 0; p < 16; p++) {
        int idx = tid + p * 256;
        int row = idx >> 5, ch = idx & 31;
        uint4 v = *(const uint4*)(g_zh + (size_t)(t0 + row) * CD_ + ch * 8);
        *(uint4*)(smem + SM_A + row * LDA_B + ch * 16) = v;
    }
    #pragma unroll
    for (int p = 0; p < 8; p++) {
        int idx = tid + p * 256;
        ((uint4*)sCN)[idx] = ((const uint4*)g_cnorm)[idx];
    }
    {
        const char* src = (const char*)g_eh;
        #pragma unroll
        for (int p = 0; p < 8; p++) {
            int idx = tid + p * 256;
            int row = idx >> 5, ch = idx & 31;
            CP_ASYNC16(su + SM_B + row * LDA_B + ch * 16, src + row * 512 + ch * 16);
        }
        CP_COMMIT();
    }

    const uint32_t aAddr = su + SM_A + (w * 16 + (l & 7) + ((l >> 3) & 1) * 8) * LDA_B
                         + (l >> 4) * 16;
    const uint32_t bOff  = ((l >> 4) * 8 + (l & 7)) * LDA_B + ((l >> 3) & 1) * 16;

    float bestA = 3.4e38f, best2A = 3.4e38f; int idxA = 0;
    float bestB = 3.4e38f, best2B = 3.4e38f; int idxB = 0;

    #pragma unroll 1
    for (int t = 0; t < K_ / 64; t++) {
        if (t + 1 < K_ / 64) {
            const char* src = (const char*)(g_eh + (size_t)(t + 1) * 64 * CD_);
            uint32_t dst = su + SM_B + ((t + 1) & 1) * B_BUF;
            #pragma unroll
            for (int p = 0; p < 8; p++) {
                int idx = tid + p * 256;
                int row = idx >> 5, ch = idx & 31;
                CP_ASYNC16(dst + row * LDA_B + ch * 16, src + row * 512 + ch * 16);
            }
            CP_COMMIT();
            asm volatile("cp.async.wait_group 1;" ::: "memory");
        } else {
            asm volatile("cp.async.wait_group 0;" ::: "memory");
        }
        __syncthreads();

        const uint32_t bBase = su + SM_B + (t & 1) * B_BUF + bOff;
        float acc[32];
        #pragma unroll
        for (int i = 0; i < 32; i++) acc[i] = 0.f;

        #pragma unroll 4
        for (int k = 0; k < 16; k++) {
            uint32_t a0, a1, a2, a3;
            ldsm4(a0, a1, a2, a3, aAddr + k * 32);
            #pragma unroll
            for (int nb = 0; nb < 4; nb++) {
                uint32_t b0, b1, b2, b3;
                ldsm4(b0, b1, b2, b3, bBase + nb * (16 * LDA_B) + k * 32);
                hmma(acc + nb * 8,     a0, a1, a2, a3, b0, b1);
                hmma(acc + nb * 8 + 4, a0, a1, a2, a3, b2, b3);
            }
        }
        __syncthreads();

        #pragma unroll
        for (int j = 0; j < 8; j++) {
            float* c = acc + (j >> 1) * 8 + (j & 1) * 4;
            int c0 = t * 64 + j * 8 + (l & 3) * 2;
            float s0 = sCN[c0]     - 2.f * c[0];
            float s1 = sCN[c0 + 1] - 2.f * c[1];
            float s2 = sCN[c0]     - 2.f * c[2];
            float s3 = sCN[c0 + 1] - 2.f * c[3];
            if (s0 < bestA) { best2A = bestA; bestA = s0; idxA = c0; }
            else if (s0 < best2A) best2A = s0;
            if (s1 < bestA) { best2A = bestA; bestA = s1; idxA = c0 + 1; }
            else if (s1 < best2A) best2A = s1;
            if (s2 < bestB) { best2B = bestB; bestB = s2; idxB = c0; }
            else if (s2 < best2B) best2B = s2;
            if (s3 < bestB) { best2B = bestB; bestB = s3; idxB = c0 + 1; }
            else if (s3 < best2B) best2B = s3;
        }
    }

    #pragma unroll
    for (int d = 1; d < 4; d <<= 1) {
        float ob  = __shfl_xor_sync(~0u, bestA, d);
        float ob2 = __shfl_xor_sync(~0u, best2A, d);
        int   oi  = __shfl_xor_sync(~0u, idxA, d);
        if (ob < bestA || (ob == bestA && oi < idxA)) {
            best2A = fminf(bestA, ob2); bestA = ob; idxA = oi;
        } else best2A = fminf(best2A, ob);
        ob  = __shfl_xor_sync(~0u, bestB, d);
        ob2 = __shfl_xor_sync(~0u, best2B, d);
        oi  = __shfl_xor_sync(~0u, idxB, d);
        if (ob < bestB || (ob == bestB && oi < idxB)) {
            best2B = fminf(bestB, ob2); bestB = ob; idxB = oi;
        } else best2B = fminf(best2B, ob);
    }
    if ((l & 3) == 0) {
        int tokA = t0 + w * 16 + (l >> 2);
        int tokB = tokA + 8;
        g_idx[tokA] = idxA;
        g_idx[tokB] = idxB;
        if (best2A - bestA < TAU) g_flags[atomicAdd(&g_flag_count, 1)] = tokA;
        if (best2B - bestB < TAU) g_flags[atomicAdd(&g_flag_count, 1)] = tokB;
    }
}

// ---------------- exact fp32 rescan v3: octant-parallel + atomicMin ----------
// unit = (token-batch of 8, codebook octant of 1024 codes = 32 tiles).
// Per-warp (token) result combined via atomicMin on key = order(score)<<32 | idx.
#define FB_TOK 8
#define FB_TILE_F (32 * 256)
__global__ __launch_bounds__(256, 1)
void fallback_kernel(const float* __restrict__ E) {
    extern __shared__ float fsm[];
    __shared__ float zs[FB_TOK][264];
    __shared__ int   stok[FB_TOK];
    const uint32_t su = smem_u32(fsm);
    int tid = threadIdx.x, w = tid >> 5, l = tid & 31;
    int cnt = g_flag_count;
    int nunits = ((cnt + FB_TOK - 1) / FB_TOK) * 8;

    for (int u = blockIdx.x; u < nunits; u += gridDim.x) {
        int tb = u >> 3, oct = u & 7;
        int base = tb * FB_TOK;
        int nt = cnt - base; if (nt > FB_TOK) nt = FB_TOK;
        __syncthreads();
        if (tid < nt) stok[tid] = g_flags[base + tid];
        __syncthreads();
        for (int i = tid; i < nt * 64; i += 256) {
            int r = i >> 6, c4 = i & 63;
            *(float4*)&zs[r][c4 * 4] =
                *(const float4*)(g_z + (size_t)stok[r] * CD_ + c4 * 4);
        }

        // prefetch tile 0 of this octant
        #pragma unroll
        for (int p = 0; p < 8; p++) {
            int i = tid + p * 256;
            int r = i >> 6, c4 = i & 63;
            uint32_t dst = su + (uint32_t)((r * 256 + (((c4 + r) & 63) << 2)) << 2);
            CP_ASYNC16(dst, (const char*)(E + (size_t)(oct * 1024 + r) * CD_) + c4 * 16);
        }
        CP_COMMIT();

        float best = 3.4e38f; int bi = 0;
        const float* zrow = zs[w < nt ? w : 0];

        #pragma unroll 1
        for (int t = 0; t < 32; t++) {
            if (t + 1 < 32) {
                const float* src = E + (size_t)(oct * 1024 + (t + 1) * 32) * CD_;
                uint32_t dstb = su + (uint32_t)((((t + 1) & 1) * FB_TILE_F) << 2);
                #pragma unroll
                for (int p = 0; p < 8; p++) {
                    int i = tid + p * 256;
                    int r = i >> 6, c4 = i & 63;
                    uint32_t dst = dstb + (uint32_t)((r * 256 + (((c4 + r) & 63) << 2)) << 2);
                    CP_ASYNC16(dst, (const char*)(src + (size_t)r * CD_) + c4 * 16);
                }
                CP_COMMIT();
                asm volatile("cp.async.wait_group 1;" ::: "memory");
            } else {
                asm volatile("cp.async.wait_group 0;" ::: "memory");
            }
            __syncthreads();

            const float* Eb = fsm + (t & 1) * FB_TILE_F + l * 256;
            float dot = 0.f;
            #pragma unroll 16
            for (int c4 = 0; c4 < 64; c4++) {
                float4 e4 = *(const float4*)(Eb + (((c4 + l) & 63) << 2));
                float4 z4 = *(const float4*)(zrow + c4 * 4);
                dot += z4.x * e4.x + z4.y * e4.y + z4.z * e4.z + z4.w * e4.w;
            }
            int code = oct * 1024 + t * 32 + l;
            float sc = __ldg(&g_cnorm[code]) - 2.f * dot;
            if (sc < best) { best = sc; bi = code; }
            __syncthreads();
        }
        // warp reduce: min score, ties -> lower index
        #pragma unroll
        for (int d = 1; d < 32; d <<= 1) {
            float ob = __shfl_xor_sync(~0u, best, d);
            int   oi = __shfl_xor_sync(~0u, bi, d);
            if (ob < best || (ob == best && oi < bi)) { best = ob; bi = oi; }
        }
        if (l == 0 && w < nt) {
            unsigned int ub = __float_as_uint(best);
            ub = (ub & 0x80000000u) ? ~ub : (ub | 0x80000000u);
            unsigned long long key = ((unsigned long long)ub << 32) | (unsigned int)bi;
            atomicMin(&g_fbkey[stok[w]], key);
        }
    }
}

__global__ void fb_write_kernel() {
    int cnt = g_flag_count;
    int stride = gridDim.x * blockDim.x;
    for (int i = blockIdx.x * blockDim.x + threadIdx.x; i < cnt; i += stride) {
        int t = g_flags[i];
        g_idx[t] = (int)(g_fbkey[t] & 0xFFFFFFFFull);
    }
}

// ---------------- gather: out[b][d][n] = Wq[idx[t]][d] + bout[d] (proven) ----
__global__ __launch_bounds__(256, 4)
void gather_out_kernel(const float* __restrict__ bout, float* __restrict__ out) {
    __shared__ float s[64][132];
    __shared__ int sidx[64];
    int nt = blockIdx.x, b = blockIdx.y;
    int tid = threadIdx.x, w = tid >> 5, l = tid & 31;
    int t0 = b * 1024 + nt * 64;
    if (tid < 64) sidx[tid] = g_idx[t0 + tid];
    __syncthreads();
    float* ob = out + (size_t)b * (D_ * HW_) + nt * 64;
    #pragma unroll 1
    for (int dc = 0; dc < 4; dc++) {
        int d0 = dc * 128;
        #pragma unroll
        for (int tk = 0; tk < 8; tk++) {
            int tok = w * 8 + tk;
            float4 v = *(const float4*)(g_wq + (size_t)sidx[tok] * D_ + d0 + l * 4);
            *(float4*)&s[tok][l * 4] = v;
        }
        __syncthreads();
        #pragma unroll
        for (int it = 0; it < 32; it++) {
            int idx = tid + it * 256;
            int d = idx >> 6, tok = idx & 63;
            ob[(size_t)(d0 + d) * HW_ + tok] = s[tok][d] + __ldg(bout + d0 + d);
        }
        __syncthreads();
    }
}

// ---------------- loss + finalize ----------------
__global__ void loss_kernel(const float* __restrict__ E) {
    __shared__ float red[256];
    int tid = threadIdx.x;
    float s = 0.f;
    int stride = gridDim.x * blockDim.x;
    for (int e = blockIdx.x * blockDim.x + tid; e < NTOK * CD_; e += stride) {
        int t = e >> 8;
        float d = E[(size_t)g_idx[t] * CD_ + (e & 255)] - g_z[e];
        s += d * d;
    }
    red[tid] = s; __syncthreads();
    for (int o = 128; o; o >>= 1) {
        if (tid < o) red[tid] += red[tid + o];
        __syncthreads();
    }
    if (tid == 0) atomicAdd(&g_loss, (double)red[0]);
}

__global__ void finalize_kernel(float* __restrict__ out, int writeIdx, int writeLoss) {
    int i = blockIdx.x * blockDim.x + threadIdx.x;
    if (writeIdx && i < NTOK) out[OUT_N + i] = (float)g_idx[i];
    if (writeLoss && i == 0)
        out[OUT_N + NTOK] = (float)(g_loss * (1.0 / (double)(NTOK * CD_)));
}

// ---------------- launch ----------------
extern "C" void kernel_launch(void* const* d_in, const int* in_sizes, int n_in,
                              void* d_out, int out_size) {
    const float* x    = (const float*)d_in[0];
    const float* Win  = (const float*)d_in[1];
    const float* bin  = (const float*)d_in[2];
    const float* Wout = (const float*)d_in[3];
    const float* bout = (const float*)d_in[4];
    const float* cb   = (const float*)d_in[5];
    float* out = (float*)d_out;

    cudaFuncSetAttribute(argmin_hmma_kernel,
                         cudaFuncAttributeMaxDynamicSharedMemorySize, SM_TOT);
    cudaFuncSetAttribute(fallback_kernel,
                         cudaFuncAttributeMaxDynamicSharedMemorySize,
                         2 * FB_TILE_F * 4);

    zero_kernel<<<1, 1>>>();
    init_fb_kernel<<<NTOK / 256, 256>>>();
    prep_codebook_kernel<<<K_ / 8, 256>>>(cb);

    dim3 g1(NTOK / 128, CD_ / 64);
    proj_in_kernel<<<g1, 256>>>(x, Win, bin);

    dim3 gq(K_ / 64, D_ / 64);
    wq_kernel<<<gq, 256>>>(cb, Wout);

    argmin_hmma_kernel<<<NTOK / 128, 256, SM_TOT>>>();
    fallback_kernel<<<512, 256, 2 * FB_TILE_F * 4>>>(cb);
    fb_write_kernel<<<16, 256>>>();

    gather_out_kernel<<<dim3(HW_ / 64, B_), 256>>>(bout, out);
    loss_kernel<<<256, 256>>>(cb);

    int writeIdx  = (out_size >= OUT_N + NTOK) ? 1 : 0;
    int writeLoss = (out_size >= OUT_N + NTOK + 1) ? 1 : 0;
    finalize_kernel<<<(NTOK + 255) / 256, 256>>>(out, writeIdx, writeLoss);
}

// round 13
// speedup vs baseline: 3.0218x; 1.0631x over previous
#include <cuda_runtime.h>
#include <cuda_fp16.h>
#include <cstdint>

#define B_    16
#define D_    512
#define HW_   1024
#define CD_   256
#define K_    8192
#define NTOK  (B_ * HW_)
#define OUT_N (B_ * D_ * HW_)
#define TAU   1e-2f

// ---------------- scratch ----------------
__device__ float  g_z[NTOK * CD_];
__device__ __half g_zh[NTOK * CD_];
__device__ __half g_eh[K_ * CD_];
__device__ float  g_wq[K_ * D_];
__device__ float  g_cnorm[K_];
__device__ int    g_idx[NTOK];
__device__ int    g_flags[NTOK];
__device__ int    g_flag_count;
__device__ unsigned long long g_fbkey[NTOK];
__device__ float  g_hb[2 * NTOK];
__device__ float  g_hb2[2 * NTOK];
__device__ int    g_hi[2 * NTOK];
__device__ double g_loss;

// ---------------- helpers ----------------
__device__ __forceinline__ uint32_t smem_u32(const void* p) {
    uint32_t a;
    asm("{ .reg .u64 t; cvta.to.shared.u64 t, %1; cvt.u32.u64 %0, t; }" : "=r"(a) : "l"(p));
    return a;
}
#define CP_ASYNC16(dst, src) \
    asm volatile("cp.async.cg.shared.global [%0], [%1], 16;" :: "r"(dst), "l"(src))
#define CP_COMMIT() asm volatile("cp.async.commit_group;" ::: "memory")

__device__ __forceinline__ void ldsm4(uint32_t& r0, uint32_t& r1, uint32_t& r2, uint32_t& r3,
                                      uint32_t addr) {
    asm volatile("ldmatrix.sync.aligned.m8n8.x4.shared.b16 {%0,%1,%2,%3}, [%4];"
                 : "=r"(r0), "=r"(r1), "=r"(r2), "=r"(r3) : "r"(addr));
}
__device__ __forceinline__ void hmma(float* c, uint32_t a0, uint32_t a1, uint32_t a2, uint32_t a3,
                                     uint32_t b0, uint32_t b1) {
    asm volatile(
        "mma.sync.aligned.m16n8k16.row.col.f32.f16.f16.f32 "
        "{%0,%1,%2,%3}, {%4,%5,%6,%7}, {%8,%9}, {%0,%1,%2,%3};"
        : "+f"(c[0]), "+f"(c[1]), "+f"(c[2]), "+f"(c[3])
        : "r"(a0), "r"(a1), "r"(a2), "r"(a3), "r"(b0), "r"(b1));
}

// argmin smem layout (bytes): A [128][264]h | B 2x[32][264]h
#define LDA_B   528
#define SM_A    0
#define SM_B    67584
#define B_BUF2  16896
#define SM_TOT2 (67584 + 2 * 16896)   /* 101376 */

// ---------------- prep: cnorm + eh ----------------
__global__ void prep_codebook_kernel(const float* __restrict__ E) {
    int warp = (blockIdx.x * blockDim.x + threadIdx.x) >> 5;
    int lane = threadIdx.x & 31;
    if (warp >= K_) return;
    const float4* row = (const float4*)(E + (size_t)warp * CD_);
    float4 a = row[lane * 2], b = row[lane * 2 + 1];
    float v[8] = {a.x, a.y, a.z, a.w, b.x, b.y, b.z, b.w};
    float s = 0.f;
    __half h[8];
    #pragma unroll
    for (int i = 0; i < 8; i++) { s += v[i] * v[i]; h[i] = __float2half(v[i]); }
    *(uint4*)(g_eh + (size_t)warp * CD_ + lane * 8) = *(uint4*)h;
    #pragma unroll
    for (int o = 16; o; o >>= 1) s += __shfl_down_sync(0xffffffffu, s, o);
    if (lane == 0) g_cnorm[warp] = s;
}

__global__ void zero_kernel() { g_loss = 0.0; g_flag_count = 0; }

__global__ void init_fb_kernel() {
    int i = blockIdx.x * blockDim.x + threadIdx.x;
    if (i < NTOK) g_fbkey[i] = 0xFFFFFFFFFFFFFFFFull;
}

// ---------------- GEMM1 v2: z = x^T W_in^T + b_in (+ fp16 copy) [proven] ------
__global__ __launch_bounds__(256, 2)
void proj_in_kernel(const float* __restrict__ x,
                    const float* __restrict__ Win,
                    const float* __restrict__ bin) {
    __shared__ float As[2][16][128];
    __shared__ float Bs[2][16][64];
    int tid = threadIdx.x;
    int tx = tid & 15, ty = tid >> 4;
    int t0 = blockIdx.x * 128, c0 = blockIdx.y * 64;
    int batch = t0 >> 10, n0 = t0 & 1023;
    const float* xb = x + (size_t)batch * (D_ * HW_);

    float acc[8][4];
    #pragma unroll
    for (int i = 0; i < 8; i++)
        #pragma unroll
        for (int j = 0; j < 4; j++) acc[i][j] = 0.f;

    int a_t = tid & 127, a_k2 = tid >> 7;
    int b_c = tid >> 2, b_k4 = tid & 3;
    float pa[8]; float4 pb;
    #pragma unroll
    for (int i = 0; i < 8; i++) pa[i] = xb[(a_k2 + 2 * i) * HW_ + n0 + a_t];
    pb = *(const float4*)(Win + (size_t)(c0 + b_c) * D_ + b_k4 * 4);
    #pragma unroll
    for (int i = 0; i < 8; i++) As[0][a_k2 + 2 * i][a_t] = pa[i];
    Bs[0][b_k4 * 4 + 0][b_c] = pb.x; Bs[0][b_k4 * 4 + 1][b_c] = pb.y;
    Bs[0][b_k4 * 4 + 2][b_c] = pb.z; Bs[0][b_k4 * 4 + 3][b_c] = pb.w;
    __syncthreads();

    #pragma unroll 1
    for (int ch = 0; ch < D_ / 16; ch++) {
        int buf = ch & 1;
        if (ch + 1 < D_ / 16) {
            int d0 = (ch + 1) * 16;
            #pragma unroll
            for (int i = 0; i < 8; i++)
                pa[i] = xb[(d0 + a_k2 + 2 * i) * HW_ + n0 + a_t];
            pb = *(const float4*)(Win + (size_t)(c0 + b_c) * D_ + d0 + b_k4 * 4);
        }
        #pragma unroll
        for (int kk = 0; kk < 16; kk++) {
            float4 a0 = *(const float4*)(&As[buf][kk][ty * 8]);
            float4 a1 = *(const float4*)(&As[buf][kk][ty * 8 + 4]);
            float4 bv = *(const float4*)(&Bs[buf][kk][tx * 4]);
            float a[8] = {a0.x, a0.y, a0.z, a0.w, a1.x, a1.y, a1.z, a1.w};
            float b[4] = {bv.x, bv.y, bv.z, bv.w};
            #pragma unroll
            for (int i = 0; i < 8; i++)
                #pragma unroll
                for (int j = 0; j < 4; j++) acc[i][j] += a[i] * b[j];
        }
        if (ch + 1 < D_ / 16) {
            int ob = buf ^ 1;
            #pragma unroll
            for (int i = 0; i < 8; i++) As[ob][a_k2 + 2 * i][a_t] = pa[i];
            Bs[ob][b_k4 * 4 + 0][b_c] = pb.x; Bs[ob][b_k4 * 4 + 1][b_c] = pb.y;
            Bs[ob][b_k4 * 4 + 2][b_c] = pb.z; Bs[ob][b_k4 * 4 + 3][b_c] = pb.w;
            __syncthreads();
        }
    }

    float4 bb = *(const float4*)(bin + c0 + tx * 4);
    float bv[4] = {bb.x, bb.y, bb.z, bb.w};
    #pragma unroll
    for (int i = 0; i < 8; i++) {
        size_t row = (size_t)(t0 + ty * 8 + i);
        float4 v;
        v.x = acc[i][0] + bv[0]; v.y = acc[i][1] + bv[1];
        v.z = acc[i][2] + bv[2]; v.w = acc[i][3] + bv[3];
        *(float4*)(g_z + row * CD_ + c0 + tx * 4) = v;
        __half h[4] = {__float2half(v.x), __float2half(v.y),
                       __float2half(v.z), __float2half(v.w)};
        *(uint2*)(g_zh + row * CD_ + c0 + tx * 4) = *(uint2*)h;
    }
}

// ---------------- Wq v2 = E W_out^T : 128x64 tile, 8x4 thread tile ----------
__global__ __launch_bounds__(256, 2)
void wq_kernel(const float* __restrict__ E,
               const float* __restrict__ Wout) {
    __shared__ float As[2][16][128];
    __shared__ float Bs[2][16][64];
    int tid = threadIdx.x;
    int tx = tid & 15, ty = tid >> 4;
    int t0 = blockIdx.x * 128, c0 = blockIdx.y * 64;

    int a_t = tid >> 1, a_h = tid & 1;     // row, 8-float half of 16-chunk
    int b_c = tid >> 2, b_k4 = tid & 3;
    const float* arow = E + (size_t)(t0 + a_t) * CD_;

    float acc[8][4];
    #pragma unroll
    for (int i = 0; i < 8; i++)
        #pragma unroll
        for (int j = 0; j < 4; j++) acc[i][j] = 0.f;

    float4 pa0 = *(const float4*)(arow + a_h * 8);
    float4 pa1 = *(const float4*)(arow + a_h * 8 + 4);
    float4 pb = *(const float4*)(Wout + (size_t)(c0 + b_c) * CD_ + b_k4 * 4);
    As[0][a_h * 8 + 0][a_t] = pa0.x; As[0][a_h * 8 + 1][a_t] = pa0.y;
    As[0][a_h * 8 + 2][a_t] = pa0.z; As[0][a_h * 8 + 3][a_t] = pa0.w;
    As[0][a_h * 8 + 4][a_t] = pa1.x; As[0][a_h * 8 + 5][a_t] = pa1.y;
    As[0][a_h * 8 + 6][a_t] = pa1.z; As[0][a_h * 8 + 7][a_t] = pa1.w;
    Bs[0][b_k4 * 4 + 0][b_c] = pb.x; Bs[0][b_k4 * 4 + 1][b_c] = pb.y;
    Bs[0][b_k4 * 4 + 2][b_c] = pb.z; Bs[0][b_k4 * 4 + 3][b_c] = pb.w;
    __syncthreads();

    #pragma unroll 1
    for (int ch = 0; ch < CD_ / 16; ch++) {
        int buf = ch & 1;
        if (ch + 1 < CD_ / 16) {
            int k0 = (ch + 1) * 16;
            pa0 = *(const float4*)(arow + k0 + a_h * 8);
            pa1 = *(const float4*)(arow + k0 + a_h * 8 + 4);
            pb = *(const float4*)(Wout + (size_t)(c0 + b_c) * CD_ + k0 + b_k4 * 4);
        }
        #pragma unroll
        for (int kk = 0; kk < 16; kk++) {
            float4 a0 = *(const float4*)(&As[buf][kk][ty * 8]);
            float4 a1 = *(const float4*)(&As[buf][kk][ty * 8 + 4]);
            float4 bv = *(const float4*)(&Bs[buf][kk][tx * 4]);
            float a[8] = {a0.x, a0.y, a0.z, a0.w, a1.x, a1.y, a1.z, a1.w};
            float b[4] = {bv.x, bv.y, bv.z, bv.w};
            #pragma unroll
            for (int i = 0; i < 8; i++)
                #pragma unroll
                for (int j = 0; j < 4; j++) acc[i][j] += a[i] * b[j];
        }
        if (ch + 1 < CD_ / 16) {
            int ob = buf ^ 1;
            As[ob][a_h * 8 + 0][a_t] = pa0.x; As[ob][a_h * 8 + 1][a_t] = pa0.y;
            As[ob][a_h * 8 + 2][a_t] = pa0.z; As[ob][a_h * 8 + 3][a_t] = pa0.w;
            As[ob][a_h * 8 + 4][a_t] = pa1.x; As[ob][a_h * 8 + 5][a_t] = pa1.y;
            As[ob][a_h * 8 + 6][a_t] = pa1.z; As[ob][a_h * 8 + 7][a_t] = pa1.w;
            Bs[ob][b_k4 * 4 + 0][b_c] = pb.x; Bs[ob][b_k4 * 4 + 1][b_c] = pb.y;
            Bs[ob][b_k4 * 4 + 2][b_c] = pb.z; Bs[ob][b_k4 * 4 + 3][b_c] = pb.w;
            __syncthreads();
        }
    }

    #pragma unroll
    for (int i = 0; i < 8; i++) {
        float4 v;
        v.x = acc[i][0]; v.y = acc[i][1]; v.z = acc[i][2]; v.w = acc[i][3];
        *(float4*)(g_wq + (size_t)(t0 + ty * 8 + i) * D_ + c0 + tx * 4) = v;
    }
}

// ---------------- HMMA argmin v2: code-split halves, 2 CTAs/SM --------------
// CTA = (token tile 128, codebook half 4096). 128 tiles of 32 codes, double-buffered.
// cnorm prefetched per-tile into registers (hidden under MMA). Per-half top-2 to global.
__global__ __launch_bounds__(256, 2)
void argmin_hmma_kernel() {
    extern __shared__ char smem[];
    const uint32_t su = smem_u32(smem);
    const int tid = threadIdx.x;
    const int w = tid >> 5, l = tid & 31;
    const int tb = blockIdx.x >> 1, half = blockIdx.x & 1;
    const int t0 = tb * 128;
    const int cb0 = half * (K_ / 2);

    #pragma unroll
    for (int p = 0; p < 16; p++) {
        int idx = tid + p * 256;
        int row = idx >> 5, ch = idx & 31;
        uint4 v = *(const uint4*)(g_zh + (size_t)(t0 + row) * CD_ + ch * 8);
        *(uint4*)(smem + SM_A + row * LDA_B + ch * 16) = v;
    }
    {
        const char* src = (const char*)(g_eh + (size_t)cb0 * CD_);
        #pragma unroll
        for (int p = 0; p < 4; p++) {
            int idx = tid + p * 256;          // 1024 chunks: 32 rows x 32
            int row = idx >> 5, ch = idx & 31;
            CP_ASYNC16(su + SM_B + row * LDA_B + ch * 16, src + row * 512 + ch * 16);
        }
        CP_COMMIT();
    }

    const uint32_t aAddr = su + SM_A + (w * 16 + (l & 7) + ((l >> 3) & 1) * 8) * LDA_B
                         + (l >> 4) * 16;
    const uint32_t bOff  = ((l >> 4) * 8 + (l & 7)) * LDA_B + ((l >> 3) & 1) * 16;

    float bestA = 3.4e38f, best2A = 3.4e38f; int idxA = 0;
    float bestB = 3.4e38f, best2B = 3.4e38f; int idxB = 0;

    #pragma unroll 1
    for (int t = 0; t < 128; t++) {
        // prefetch cnorm for this tile's epilogue (hidden under the MMAs)
        float cn[8];
        #pragma unroll
        for (int j = 0; j < 4; j++) {
            int c0 = cb0 + t * 32 + j * 8 + (l & 3) * 2;
            cn[j * 2]     = __ldg(&g_cnorm[c0]);
            cn[j * 2 + 1] = __ldg(&g_cnorm[c0 + 1]);
        }
        if (t + 1 < 128) {
            const char* src = (const char*)(g_eh + (size_t)(cb0 + (t + 1) * 32) * CD_);
            uint32_t dst = su + SM_B + ((t + 1) & 1) * B_BUF2;
            #pragma unroll
            for (int p = 0; p < 4; p++) {
                int idx = tid + p * 256;
                int row = idx >> 5, ch = idx & 31;
                CP_ASYNC16(dst + row * LDA_B + ch * 16, src + row * 512 + ch * 16);
            }
            CP_COMMIT();
            asm volatile("cp.async.wait_group 1;" ::: "memory");
        } else {
            asm volatile("cp.async.wait_group 0;" ::: "memory");
        }
        __syncthreads();

        const uint32_t bBase = su + SM_B + (t & 1) * B_BUF2 + bOff;
        float acc[16];
        #pragma unroll
        for (int i = 0; i < 16; i++) acc[i] = 0.f;

        #pragma unroll 4
        for (int k = 0; k < 16; k++) {
            uint32_t a0, a1, a2, a3;
            ldsm4(a0, a1, a2, a3, aAddr + k * 32);
            #pragma unroll
            for (int nb = 0; nb < 2; nb++) {
                uint32_t b0, b1, b2, b3;
                ldsm4(b0, b1, b2, b3, bBase + nb * (16 * LDA_B) + k * 32);
                hmma(acc + nb * 8,     a0, a1, a2, a3, b0, b1);
                hmma(acc + nb * 8 + 4, a0, a1, a2, a3, b2, b3);
            }
        }
        __syncthreads();

        #pragma unroll
        for (int j = 0; j < 4; j++) {
            float* c = acc + (j >> 1) * 8 + (j & 1) * 4;
            int c0 = cb0 + t * 32 + j * 8 + (l & 3) * 2;
            float s0 = cn[j * 2]     - 2.f * c[0];
            float s1 = cn[j * 2 + 1] - 2.f * c[1];
            float s2 = cn[j * 2]     - 2.f * c[2];
            float s3 = cn[j * 2 + 1] - 2.f * c[3];
            if (s0 < bestA) { best2A = bestA; bestA = s0; idxA = c0; }
            else if (s0 < best2A) best2A = s0;
            if (s1 < bestA) { best2A = bestA; bestA = s1; idxA = c0 + 1; }
            else if (s1 < best2A) best2A = s1;
            if (s2 < bestB) { best2B = bestB; bestB = s2; idxB = c0; }
            else if (s2 < best2B) best2B = s2;
            if (s3 < bestB) { best2B = bestB; bestB = s3; idxB = c0 + 1; }
            else if (s3 < best2B) best2B = s3;
        }
    }

    #pragma unroll
    for (int d = 1; d < 4; d <<= 1) {
        float ob  = __shfl_xor_sync(~0u, bestA, d);
        float ob2 = __shfl_xor_sync(~0u, best2A, d);
        int   oi  = __shfl_xor_sync(~0u, idxA, d);
        if (ob < bestA || (ob == bestA && oi < idxA)) {
            best2A = fminf(bestA, ob2); bestA = ob; idxA = oi;
        } else best2A = fminf(best2A, ob);
        ob  = __shfl_xor_sync(~0u, bestB, d);
        ob2 = __shfl_xor_sync(~0u, best2B, d);
        oi  = __shfl_xor_sync(~0u, idxB, d);
        if (ob < bestB || (ob == bestB && oi < idxB)) {
            best2B = fminf(bestB, ob2); bestB = ob; idxB = oi;
        } else best2B = fminf(best2B, ob);
    }
    if ((l & 3) == 0) {
        int tokA = t0 + w * 16 + (l >> 2);
        int tokB = tokA + 8;
        int oA = half * NTOK + tokA;
        int oB = half * NTOK + tokB;
        g_hb[oA] = bestA; g_hb2[oA] = best2A; g_hi[oA] = idxA;
        g_hb[oB] = bestB; g_hb2[oB] = best2B; g_hi[oB] = idxB;
    }
}

// ---------------- combine halves: exact winner + TAU flagging ----------------
__global__ void combine_kernel() {
    int t = blockIdx.x * blockDim.x + threadIdx.x;
    if (t >= NTOK) return;
    float bA = g_hb[t],        b2A = g_hb2[t];        int iA = g_hi[t];
    float bB = g_hb[NTOK + t], b2B = g_hb2[NTOK + t]; int iB = g_hi[NTOK + t];
    float fb, fb2; int fi;
    if (bB < bA) { fb = bB; fi = iB; fb2 = fminf(bA, b2B); }
    else         { fb = bA; fi = iA; fb2 = fminf(bB, b2A); }   // tie -> half0 = lower idx
    g_idx[t] = fi;
    if (fb2 - fb < TAU) g_flags[atomicAdd(&g_flag_count, 1)] = t;
}

// ---------------- exact fp32 rescan v3 (proven) ----------------
#define FB_TOK 8
#define FB_TILE_F (32 * 256)
__global__ __launch_bounds__(256, 1)
void fallback_kernel(const float* __restrict__ E) {
    extern __shared__ float fsm[];
    __shared__ float zs[FB_TOK][264];
    __shared__ int   stok[FB_TOK];
    const uint32_t su = smem_u32(fsm);
    int tid = threadIdx.x, w = tid >> 5, l = tid & 31;
    int cnt = g_flag_count;
    int nunits = ((cnt + FB_TOK - 1) / FB_TOK) * 8;

    for (int u = blockIdx.x; u < nunits; u += gridDim.x) {
        int tb = u >> 3, oct = u & 7;
        int base = tb * FB_TOK;
        int nt = cnt - base; if (nt > FB_TOK) nt = FB_TOK;
        __syncthreads();
        if (tid < nt) stok[tid] = g_flags[base + tid];
        __syncthreads();
        for (int i = tid; i < nt * 64; i += 256) {
            int r = i >> 6, c4 = i & 63;
            *(float4*)&zs[r][c4 * 4] =
                *(const float4*)(g_z + (size_t)stok[r] * CD_ + c4 * 4);
        }
        #pragma unroll
        for (int p = 0; p < 8; p++) {
            int i = tid + p * 256;
            int r = i >> 6, c4 = i & 63;
            uint32_t dst = su + (uint32_t)((r * 256 + (((c4 + r) & 63) << 2)) << 2);
            CP_ASYNC16(dst, (const char*)(E + (size_t)(oct * 1024 + r) * CD_) + c4 * 16);
        }
        CP_COMMIT();

        float best = 3.4e38f; int bi = 0;
        const float* zrow = zs[w < nt ? w : 0];

        #pragma unroll 1
        for (int t = 0; t < 32; t++) {
            if (t + 1 < 32) {
                const float* src = E + (size_t)(oct * 1024 + (t + 1) * 32) * CD_;
                uint32_t dstb = su + (uint32_t)((((t + 1) & 1) * FB_TILE_F) << 2);
                #pragma unroll
                for (int p = 0; p < 8; p++) {
                    int i = tid + p * 256;
                    int r = i >> 6, c4 = i & 63;
                    uint32_t dst = dstb + (uint32_t)((r * 256 + (((c4 + r) & 63) << 2)) << 2);
                    CP_ASYNC16(dst, (const char*)(src + (size_t)r * CD_) + c4 * 16);
                }
                CP_COMMIT();
                asm volatile("cp.async.wait_group 1;" ::: "memory");
            } else {
                asm volatile("cp.async.wait_group 0;" ::: "memory");
            }
            __syncthreads();

            const float* Eb = fsm + (t & 1) * FB_TILE_F + l * 256;
            float dot = 0.f;
            #pragma unroll 16
            for (int c4 = 0; c4 < 64; c4++) {
                float4 e4 = *(const float4*)(Eb + (((c4 + l) & 63) << 2));
                float4 z4 = *(const float4*)(zrow + c4 * 4);
                dot += z4.x * e4.x + z4.y * e4.y + z4.z * e4.z + z4.w * e4.w;
            }
            int code = oct * 1024 + t * 32 + l;
            float sc = __ldg(&g_cnorm[code]) - 2.f * dot;
            if (sc < best) { best = sc; bi = code; }
            __syncthreads();
        }
        #pragma unroll
        for (int d = 1; d < 32; d <<= 1) {
            float ob = __shfl_xor_sync(~0u, best, d);
            int   oi = __shfl_xor_sync(~0u, bi, d);
            if (ob < best || (ob == best && oi < bi)) { best = ob; bi = oi; }
        }
        if (l == 0 && w < nt) {
            unsigned int ub = __float_as_uint(best);
            ub = (ub & 0x80000000u) ? ~ub : (ub | 0x80000000u);
            unsigned long long key = ((unsigned long long)ub << 32) | (unsigned int)bi;
            atomicMin(&g_fbkey[stok[w]], key);
        }
    }
}

__global__ void fb_write_kernel() {
    int cnt = g_flag_count;
    int stride = gridDim.x * blockDim.x;
    for (int i = blockIdx.x * blockDim.x + threadIdx.x; i < cnt; i += stride) {
        int t = g_flags[i];
        g_idx[t] = (int)(g_fbkey[t] & 0xFFFFFFFFull);
    }
}

// ---------------- gather (proven) ----------------
__global__ __launch_bounds__(256, 4)
void gather_out_kernel(const float* __restrict__ bout, float* __restrict__ out) {
    __shared__ float s[64][132];
    __shared__ int sidx[64];
    int nt = blockIdx.x, b = blockIdx.y;
    int tid = threadIdx.x, w = tid >> 5, l = tid & 31;
    int t0 = b * 1024 + nt * 64;
    if (tid < 64) sidx[tid] = g_idx[t0 + tid];
    __syncthreads();
    float* ob = out + (size_t)b * (D_ * HW_) + nt * 64;
    #pragma unroll 1
    for (int dc = 0; dc < 4; dc++) {
        int d0 = dc * 128;
        #pragma unroll
        for (int tk = 0; tk < 8; tk++) {
            int tok = w * 8 + tk;
            float4 v = *(const float4*)(g_wq + (size_t)sidx[tok] * D_ + d0 + l * 4);
            *(float4*)&s[tok][l * 4] = v;
        }
        __syncthreads();
        #pragma unroll
        for (int it = 0; it < 32; it++) {
            int idx = tid + it * 256;
            int d = idx >> 6, tok = idx & 63;
            ob[(size_t)(d0 + d) * HW_ + tok] = s[tok][d] + __ldg(bout + d0 + d);
        }
        __syncthreads();
    }
}

// ---------------- loss + finalize ----------------
__global__ void loss_kernel(const float* __restrict__ E) {
    __shared__ float red[256];
    int tid = threadIdx.x;
    float s = 0.f;
    int stride = gridDim.x * blockDim.x;
    for (int e = blockIdx.x * blockDim.x + tid; e < NTOK * CD_; e += stride) {
        int t = e >> 8;
        float d = E[(size_t)g_idx[t] * CD_ + (e & 255)] - g_z[e];
        s += d * d;
    }
    red[tid] = s; __syncthreads();
    for (int o = 128; o; o >>= 1) {
        if (tid < o) red[tid] += red[tid + o];
        __syncthreads();
    }
    if (tid == 0) atomicAdd(&g_loss, (double)red[0]);
}

__global__ void finalize_kernel(float* __restrict__ out, int writeIdx, int writeLoss) {
    int i = blockIdx.x * blockDim.x + threadIdx.x;
    if (writeIdx && i < NTOK) out[OUT_N + i] = (float)g_idx[i];
    if (writeLoss && i == 0)
        out[OUT_N + NTOK] = (float)(g_loss * (1.0 / (double)(NTOK * CD_)));
}

// ---------------- launch ----------------
extern "C" void kernel_launch(void* const* d_in, const int* in_sizes, int n_in,
                              void* d_out, int out_size) {
    const float* x    = (const float*)d_in[0];
    const float* Win  = (const float*)d_in[1];
    const float* bin  = (const float*)d_in[2];
    const float* Wout = (const float*)d_in[3];
    const float* bout = (const float*)d_in[4];
    const float* cb   = (const float*)d_in[5];
    float* out = (float*)d_out;

    cudaFuncSetAttribute(argmin_hmma_kernel,
                         cudaFuncAttributeMaxDynamicSharedMemorySize, SM_TOT2);
    cudaFuncSetAttribute(fallback_kernel,
                         cudaFuncAttributeMaxDynamicSharedMemorySize,
                         2 * FB_TILE_F * 4);

    zero_kernel<<<1, 1>>>();
    init_fb_kernel<<<NTOK / 256, 256>>>();
    prep_codebook_kernel<<<K_ / 8, 256>>>(cb);

    dim3 g1(NTOK / 128, CD_ / 64);
    proj_in_kernel<<<g1, 256>>>(x, Win, bin);

    dim3 gq(K_ / 128, D_ / 64);
    wq_kernel<<<gq, 256>>>(cb, Wout);

    argmin_hmma_kernel<<<2 * NTOK / 128, 256, SM_TOT2>>>();
    combine_kernel<<<NTOK / 256, 256>>>();
    fallback_kernel<<<512, 256, 2 * FB_TILE_F * 4>>>(cb);
    fb_write_kernel<<<16, 256>>>();

    gather_out_kernel<<<dim3(HW_ / 64, B_), 256>>>(bout, out);
    loss_kernel<<<256, 256>>>(cb);

    int writeIdx  = (out_size >= OUT_N + NTOK) ? 1 : 0;
    int writeLoss = (out_size >= OUT_N + NTOK + 1) ? 1 : 0;
    finalize_kernel<<<(NTOK + 255) / 256, 256>>>(out, writeIdx, writeLoss);
}